// round 15
// baseline (speedup 1.0000x reference)
#include <cuda_runtime.h>
#include <cuda_bf16.h>
#include <cstdint>

#define NTS  4096
#define SEQL 168
#define HOR  24
#define TT   192
#define TR   (NTS*SEQL)   // 688128 teacher rows
#define FR   (NTS*HOR)    // 98304 forecast rows

typedef unsigned long long u64;
typedef unsigned int u32;

// ---- device scratch ----------------------------------------------------------
__device__ __nv_bfloat16 g_h1hi[(size_t)TR * 64];   // [row][u] bf16 hi
__device__ __nv_bfloat16 g_h1lo[(size_t)TR * 64];   // [row][u] bf16 lo
__device__ float g_Gx[(size_t)HOR * 192 * NTS];     // [tp][j][n]
__device__ float g_carry[NTS];
__device__ float g_mu_fb[NTS * TT];
__device__ float g_sg_fb[NTS * TT];
// pre-split planar W1 images: [j 0..191 gate-major][k 0..63] bf16
__device__ __nv_bfloat16 g_Bhi[192 * 64];
__device__ __nv_bfloat16 g_Blo[192 * 64];

__device__ __forceinline__ int rowsel(int g, int u) {
    // torch gate rows: i=[0,64) f=[64,128) g=[128,192) o=[192,256); f skipped
    return (g == 0) ? u : ((g == 1) ? 128 + u : 192 + u);
}
__device__ __forceinline__ float tanhapx(float x) {
    float r; asm("tanh.approx.f32 %0, %1;" : "=f"(r) : "f"(x)); return r;
}
__device__ __forceinline__ float sigapx(float x) {
    return fmaf(0.5f, tanhapx(0.5f * x), 0.5f);
}
__device__ __forceinline__ float fsoftplus(float x) {
    return (x > 15.f) ? x : __logf(1.f + __expf(x));
}

// ---- packed f32x2 helpers ----------------------------------------------------
__device__ __forceinline__ u64 pack2(float lo, float hi) {
    u64 r; asm("mov.b64 %0, {%1, %2};" : "=l"(r) : "f"(lo), "f"(hi)); return r;
}
__device__ __forceinline__ void unpack2(u64 v, float& lo, float& hi) {
    asm("mov.b64 {%0, %1}, %2;" : "=f"(lo), "=f"(hi) : "l"(v));
}
__device__ __forceinline__ u64 ffma2(u64 a, u64 b, u64 c) {
    u64 d; asm("fma.rn.f32x2 %0, %1, %2, %3;" : "=l"(d) : "l"(a), "l"(b), "l"(c));
    return d;
}

// ---- warp-level bf16 MMA (sm_80 base feature; legal at target sm_103) --------
__device__ __forceinline__ void mma_bf16(float d[4], u32 a0, u32 a1, u32 a2,
                                         u32 a3, u32 b0, u32 b1) {
    asm volatile(
        "mma.sync.aligned.m16n8k16.row.col.f32.bf16.bf16.f32 "
        "{%0,%1,%2,%3}, {%4,%5,%6,%7}, {%8,%9}, {%0,%1,%2,%3};"
        : "+f"(d[0]), "+f"(d[1]), "+f"(d[2]), "+f"(d[3])
        : "r"(a0), "r"(a1), "r"(a2), "r"(a3), "r"(b0), "r"(b1));
}

// =============================================================================
// P1a / P1b shared layout (floats)  [unchanged]
#define SMA_W   0
#define SMA_X   6176
#define SMA_Y   10400
#define SMA_V   10528
#define SMA_C0  10720
#define SMA_FLOATS 10912
#define SMA_BYTES (SMA_FLOATS * 4)

#define GATE_FFMA2_16(wi2, wg2, wo2, xa, xb, xc, xd)                      \
    ai2[0]=ffma2(wi2, xa.x, ai2[0]); ai2[1]=ffma2(wi2, xa.y, ai2[1]);     \
    ai2[2]=ffma2(wi2, xb.x, ai2[2]); ai2[3]=ffma2(wi2, xb.y, ai2[3]);     \
    ai2[4]=ffma2(wi2, xc.x, ai2[4]); ai2[5]=ffma2(wi2, xc.y, ai2[5]);     \
    ai2[6]=ffma2(wi2, xd.x, ai2[6]); ai2[7]=ffma2(wi2, xd.y, ai2[7]);     \
    ag2[0]=ffma2(wg2, xa.x, ag2[0]); ag2[1]=ffma2(wg2, xa.y, ag2[1]);     \
    ag2[2]=ffma2(wg2, xb.x, ag2[2]); ag2[3]=ffma2(wg2, xb.y, ag2[3]);     \
    ag2[4]=ffma2(wg2, xc.x, ag2[4]); ag2[5]=ffma2(wg2, xc.y, ag2[5]);     \
    ag2[6]=ffma2(wg2, xd.x, ag2[6]); ag2[7]=ffma2(wg2, xd.y, ag2[7]);     \
    ao2[0]=ffma2(wo2, xa.x, ao2[0]); ao2[1]=ffma2(wo2, xa.y, ao2[1]);     \
    ao2[2]=ffma2(wo2, xb.x, ao2[2]); ao2[3]=ffma2(wo2, xb.y, ao2[3]);     \
    ao2[4]=ffma2(wo2, xc.x, ao2[4]); ao2[5]=ffma2(wo2, xc.y, ao2[5]);     \
    ao2[6]=ffma2(wo2, xd.x, ao2[6]); ao2[7]=ffma2(wo2, xd.y, ao2[7]);

// ---- P1a: layer0 for teacher rows, writes h1 as bf16 hi/lo -------------------
__global__ void __launch_bounds__(256, 2) kP1a(
    const float* __restrict__ X, const float* __restrict__ y,
    const float* __restrict__ W_ih, const float* __restrict__ b_ih,
    const float* __restrict__ b_hh, const float* __restrict__ W_embed,
    const float* __restrict__ b_embed)
{
    extern __shared__ float sm[];
    int tid = threadIdx.x;
    for (int i = tid; i < 6144; i += 256) {
        int g = i >> 11, u = (i >> 5) & 63, k = i & 31;
        sm[SMA_W + k * 193 + g * 64 + u] = W_ih[rowsel(g, u) * 64 + k];
    }
    for (int j = tid; j < 192; j += 256) {
        int g = j >> 6, u = j & 63, row = rowsel(g, u);
        float v = 0.f, cb = 0.f;
        #pragma unroll
        for (int e = 0; e < 32; e++) {
            float w = W_ih[row * 64 + 32 + e];
            v = fmaf(w, W_embed[e], v); cb = fmaf(w, b_embed[e], cb);
        }
        sm[SMA_V + j] = v;
        sm[SMA_C0 + j] = b_ih[row] + b_hh[row] + cb;
    }
    int rowbase = blockIdx.x * 128;
    const float* xg = X + (size_t)rowbase * 32;
    for (int i = tid; i < 4096; i += 256)
        sm[SMA_X + (i & 31) * 132 + (i >> 5)] = xg[i];
    for (int i = tid; i < 128; i += 256) sm[SMA_Y + i] = y[rowbase + i];
    __syncthreads();

    int u = tid & 63, rg = tid >> 6;
    float vi = sm[SMA_V + u], vg = sm[SMA_V + 64 + u], vo = sm[SMA_V + 128 + u];
    float ci = sm[SMA_C0 + u], cg0 = sm[SMA_C0 + 64 + u], co = sm[SMA_C0 + 128 + u];

    #pragma unroll 1
    for (int rr = 0; rr < 2; rr++) {
        int r0 = rg * 32 + rr * 16;
        u64 ai2[8], ag2[8], ao2[8];
        #pragma unroll
        for (int p = 0; p < 8; p++) {
            float y0 = sm[SMA_Y + r0 + 2 * p], y1 = sm[SMA_Y + r0 + 2 * p + 1];
            ai2[p] = pack2(fmaf(y0, vi, ci),  fmaf(y1, vi, ci));
            ag2[p] = pack2(fmaf(y0, vg, cg0), fmaf(y1, vg, cg0));
            ao2[p] = pack2(fmaf(y0, vo, co),  fmaf(y1, vo, co));
        }
        #pragma unroll 4
        for (int k = 0; k < 32; k++) {
            float wi = sm[SMA_W + k * 193 + u];
            float wg = sm[SMA_W + k * 193 + 64 + u];
            float wo = sm[SMA_W + k * 193 + 128 + u];
            u64 wi2 = pack2(wi, wi), wg2 = pack2(wg, wg), wo2 = pack2(wo, wo);
            ulonglong2 xa = *(const ulonglong2*)&sm[SMA_X + k * 132 + r0];
            ulonglong2 xb = *(const ulonglong2*)&sm[SMA_X + k * 132 + r0 + 4];
            ulonglong2 xc = *(const ulonglong2*)&sm[SMA_X + k * 132 + r0 + 8];
            ulonglong2 xd = *(const ulonglong2*)&sm[SMA_X + k * 132 + r0 + 12];
            GATE_FFMA2_16(wi2, wg2, wo2, xa, xb, xc, xd)
        }
        #pragma unroll
        for (int p = 0; p < 8; p++) {
            float a0, a1, b0, b1, c0, c1;
            unpack2(ai2[p], a0, a1); unpack2(ag2[p], b0, b1); unpack2(ao2[p], c0, c1);
            float cc0 = sigapx(a0) * tanhapx(b0);
            float cc1 = sigapx(a1) * tanhapx(b1);
            float h0v = sigapx(c0) * tanhapx(cc0);
            float h1v = sigapx(c1) * tanhapx(cc1);
            size_t i0 = (size_t)(rowbase + r0 + 2 * p) * 64 + u;
            size_t i1 = (size_t)(rowbase + r0 + 2 * p + 1) * 64 + u;
            __nv_bfloat16 h0h = __float2bfloat16(h0v);
            __nv_bfloat16 h1h = __float2bfloat16(h1v);
            g_h1hi[i0] = h0h;
            g_h1lo[i0] = __float2bfloat16(h0v - __bfloat162float(h0h));
            g_h1hi[i1] = h1h;
            g_h1lo[i1] = __float2bfloat16(h1v - __bfloat162float(h1h));
        }
    }
}

// ---- P1b: layer0 x-part for forecast rows, writes Gx (unchanged) ------------
__global__ void __launch_bounds__(256, 2) kP1b(
    const float* __restrict__ Xf,
    const float* __restrict__ W_ih, const float* __restrict__ b_ih,
    const float* __restrict__ b_hh, const float* __restrict__ b_embed)
{
    extern __shared__ float sm[];
    int tid = threadIdx.x;
    for (int i = tid; i < 6144; i += 256) {
        int g = i >> 11, u = (i >> 5) & 63, k = i & 31;
        sm[SMA_W + k * 193 + g * 64 + u] = W_ih[rowsel(g, u) * 64 + k];
    }
    for (int j = tid; j < 192; j += 256) {
        int g = j >> 6, u = j & 63, row = rowsel(g, u);
        float cb = 0.f;
        #pragma unroll
        for (int e = 0; e < 32; e++)
            cb = fmaf(W_ih[row * 64 + 32 + e], b_embed[e], cb);
        sm[SMA_C0 + j] = b_ih[row] + b_hh[row] + cb;
    }
    int tp = blockIdx.y, nbase = blockIdx.x * 128;
    for (int i = tid; i < 4096; i += 256) {
        int r = i >> 5, k = i & 31;
        sm[SMA_X + k * 132 + r] = Xf[((size_t)(nbase + r) * HOR + tp) * 32 + k];
    }
    __syncthreads();

    int u = tid & 63, rg = tid >> 6;
    float ci = sm[SMA_C0 + u], cg0 = sm[SMA_C0 + 64 + u], co = sm[SMA_C0 + 128 + u];

    #pragma unroll 1
    for (int rr = 0; rr < 2; rr++) {
        int r0 = rg * 32 + rr * 16;
        u64 ai2[8], ag2[8], ao2[8];
        #pragma unroll
        for (int p = 0; p < 8; p++) {
            ai2[p] = pack2(ci, ci);
            ag2[p] = pack2(cg0, cg0);
            ao2[p] = pack2(co, co);
        }
        #pragma unroll 4
        for (int k = 0; k < 32; k++) {
            float wi = sm[SMA_W + k * 193 + u];
            float wg = sm[SMA_W + k * 193 + 64 + u];
            float wo = sm[SMA_W + k * 193 + 128 + u];
            u64 wi2 = pack2(wi, wi), wg2 = pack2(wg, wg), wo2 = pack2(wo, wo);
            ulonglong2 xa = *(const ulonglong2*)&sm[SMA_X + k * 132 + r0];
            ulonglong2 xb = *(const ulonglong2*)&sm[SMA_X + k * 132 + r0 + 4];
            ulonglong2 xc = *(const ulonglong2*)&sm[SMA_X + k * 132 + r0 + 8];
            ulonglong2 xd = *(const ulonglong2*)&sm[SMA_X + k * 132 + r0 + 12];
            GATE_FFMA2_16(wi2, wg2, wo2, xa, xb, xc, xd)
        }
        u64* gi = (u64*)&g_Gx[((size_t)tp * 192 + u) * 4096 + nbase + r0];
        u64* gg = (u64*)&g_Gx[((size_t)tp * 192 + 64 + u) * 4096 + nbase + r0];
        u64* go = (u64*)&g_Gx[((size_t)tp * 192 + 128 + u) * 4096 + nbase + r0];
        #pragma unroll
        for (int p = 0; p < 4; p++) {
            *(ulonglong2*)(gi + 2 * p) = make_ulonglong2(ai2[2 * p], ai2[2 * p + 1]);
            *(ulonglong2*)(gg + 2 * p) = make_ulonglong2(ag2[2 * p], ag2[2 * p + 1]);
            *(ulonglong2*)(go + 2 * p) = make_ulonglong2(ao2[2 * p], ao2[2 * p + 1]);
        }
    }
}

// =============================================================================
// kPrepB: split W1 into bf16 hi/lo planar images [j][k] (once per launch)
__global__ void kPrepB(const float* __restrict__ W_ih)
{
    int idx = blockIdx.x * 256 + threadIdx.x;
    if (idx >= 192 * 64) return;
    int j = idx >> 6, k = idx & 63;
    int row = rowsel(j >> 6, j & 63);
    float w = W_ih[16384 + row * 64 + k];
    __nv_bfloat16 hi = __float2bfloat16(w);
    __nv_bfloat16 lo = __float2bfloat16(w - __bfloat162float(hi));
    g_Bhi[j * 64 + k] = hi;
    g_Blo[j * 64 + k] = lo;
}

// =============================================================================
// kP2tc: layer1 + head via warp-level bf16-split mma.sync, register epilogue.
// Block = 256 threads (8 warps), 128 rows. Warp w owns rows [w*16, w*16+16).
// smem (bytes):
#define T2_AHI  0                      // 128 x 72 bf16 = 18432
#define T2_ALO  18432
#define T2_BHI  36864                  // 192 x 72 bf16 = 27648
#define T2_BLO  64512
#define T2_C1   92160                  // 192 f32
#define T2_WMU  (T2_C1 + 768)          // 64 f32
#define T2_WSG  (T2_WMU + 256)         // 64 f32
#define T2_BYTES (T2_WSG + 256 + 128)  // ~91.6 KB -> 2 blocks/SM

__global__ void __launch_bounds__(256, 2) kP2tc(
    const float* __restrict__ b_ih, const float* __restrict__ b_hh,
    const float* __restrict__ W_mu, const float* __restrict__ b_mu,
    const float* __restrict__ W_sigma, const float* __restrict__ b_sigma,
    const float* __restrict__ y,
    float* __restrict__ out_yp, float* __restrict__ out_mu,
    float* __restrict__ out_sg)
{
    extern __shared__ char smc[];
    float* smf = (float*)smc;
    int tid = threadIdx.x;
    int rowbase = blockIdx.x * 128;

    // stage A: copy pre-split bf16 hi/lo (u32 = 2 bf16), pad-72 rows
    {
        const u32* hh = (const u32*)g_h1hi + (size_t)rowbase * 32;
        const u32* hl = (const u32*)g_h1lo + (size_t)rowbase * 32;
        for (int i = tid; i < 4096; i += 256) {
            int r = i >> 5, kw = i & 31;
            *(u32*)(smc + T2_AHI + (r * 72 + kw * 2) * 2) = hh[i];
            *(u32*)(smc + T2_ALO + (r * 72 + kw * 2) * 2) = hl[i];
        }
    }
    // stage B: planar [192][64] -> pad-72 rows
    {
        const u32* sh = (const u32*)g_Bhi;
        const u32* sl = (const u32*)g_Blo;
        for (int i = tid; i < 192 * 32; i += 256) {
            int j = i >> 5, kw = i & 31;
            *(u32*)(smc + T2_BHI + (j * 72 + kw * 2) * 2) = sh[i];
            *(u32*)(smc + T2_BLO + (j * 72 + kw * 2) * 2) = sl[i];
        }
    }
    // biases + head weights
    for (int j = tid; j < 192; j += 256) {
        int row = rowsel(j >> 6, j & 63);
        smf[T2_C1 / 4 + j] = b_ih[256 + row] + b_hh[256 + row];
    }
    if (tid < 64) {
        smf[T2_WMU / 4 + tid] = W_mu[tid];
        smf[T2_WSG / 4 + tid] = W_sigma[tid];
    }
    __syncthreads();

    int w = tid >> 5, lane = tid & 31;
    int g = lane >> 2, tig = lane & 3;
    int r0 = w * 16;

    // hoist A fragments for all 4 k-steps (hi and lo)
    u32 Ah[4][4], Al[4][4];
    #pragma unroll
    for (int ks = 0; ks < 4; ks++) {
        int kb = ks * 16;
        int ra = r0 + g, rb = r0 + g + 8;
        Ah[ks][0] = *(const u32*)(smc + T2_AHI + (ra * 72 + kb + 2 * tig) * 2);
        Ah[ks][1] = *(const u32*)(smc + T2_AHI + (rb * 72 + kb + 2 * tig) * 2);
        Ah[ks][2] = *(const u32*)(smc + T2_AHI + (ra * 72 + kb + 8 + 2 * tig) * 2);
        Ah[ks][3] = *(const u32*)(smc + T2_AHI + (rb * 72 + kb + 8 + 2 * tig) * 2);
        Al[ks][0] = *(const u32*)(smc + T2_ALO + (ra * 72 + kb + 2 * tig) * 2);
        Al[ks][1] = *(const u32*)(smc + T2_ALO + (rb * 72 + kb + 2 * tig) * 2);
        Al[ks][2] = *(const u32*)(smc + T2_ALO + (ra * 72 + kb + 8 + 2 * tig) * 2);
        Al[ks][3] = *(const u32*)(smc + T2_ALO + (rb * 72 + kb + 8 + 2 * tig) * 2);
    }

    // MMA + in-register epilogue: loop over 8 unit-groups; per group compute
    // the i/g/o tiles (cols un0, 64+un0, 128+un0) then the nonlinear head for
    // units un0+2tig, un0+2tig+1, rows r0+g and r0+g+8.
    float muA = 0.f, sgA = 0.f, muB = 0.f, sgB = 0.f;
    #pragma unroll 1
    for (int un0 = 0; un0 < 64; un0 += 8) {
        float di[4] = {0.f, 0.f, 0.f, 0.f};
        float dg[4] = {0.f, 0.f, 0.f, 0.f};
        float dq[4] = {0.f, 0.f, 0.f, 0.f};
        int nbi = un0 + g, nbg = 64 + un0 + g, nbo = 128 + un0 + g;
        #pragma unroll
        for (int ks = 0; ks < 4; ks++) {
            int kb = ks * 16;
            u32 bh0, bh1, bl0, bl1;
            // i-gate tile
            bh0 = *(const u32*)(smc + T2_BHI + (nbi * 72 + kb + 2 * tig) * 2);
            bh1 = *(const u32*)(smc + T2_BHI + (nbi * 72 + kb + 8 + 2 * tig) * 2);
            bl0 = *(const u32*)(smc + T2_BLO + (nbi * 72 + kb + 2 * tig) * 2);
            bl1 = *(const u32*)(smc + T2_BLO + (nbi * 72 + kb + 8 + 2 * tig) * 2);
            mma_bf16(di, Ah[ks][0], Ah[ks][1], Ah[ks][2], Ah[ks][3], bh0, bh1);
            mma_bf16(di, Ah[ks][0], Ah[ks][1], Ah[ks][2], Ah[ks][3], bl0, bl1);
            mma_bf16(di, Al[ks][0], Al[ks][1], Al[ks][2], Al[ks][3], bh0, bh1);
            // g-gate tile
            bh0 = *(const u32*)(smc + T2_BHI + (nbg * 72 + kb + 2 * tig) * 2);
            bh1 = *(const u32*)(smc + T2_BHI + (nbg * 72 + kb + 8 + 2 * tig) * 2);
            bl0 = *(const u32*)(smc + T2_BLO + (nbg * 72 + kb + 2 * tig) * 2);
            bl1 = *(const u32*)(smc + T2_BLO + (nbg * 72 + kb + 8 + 2 * tig) * 2);
            mma_bf16(dg, Ah[ks][0], Ah[ks][1], Ah[ks][2], Ah[ks][3], bh0, bh1);
            mma_bf16(dg, Ah[ks][0], Ah[ks][1], Ah[ks][2], Ah[ks][3], bl0, bl1);
            mma_bf16(dg, Al[ks][0], Al[ks][1], Al[ks][2], Al[ks][3], bh0, bh1);
            // o-gate tile
            bh0 = *(const u32*)(smc + T2_BHI + (nbo * 72 + kb + 2 * tig) * 2);
            bh1 = *(const u32*)(smc + T2_BHI + (nbo * 72 + kb + 8 + 2 * tig) * 2);
            bl0 = *(const u32*)(smc + T2_BLO + (nbo * 72 + kb + 2 * tig) * 2);
            bl1 = *(const u32*)(smc + T2_BLO + (nbo * 72 + kb + 8 + 2 * tig) * 2);
            mma_bf16(dq, Ah[ks][0], Ah[ks][1], Ah[ks][2], Ah[ks][3], bh0, bh1);
            mma_bf16(dq, Ah[ks][0], Ah[ks][1], Ah[ks][2], Ah[ks][3], bl0, bl1);
            mma_bf16(dq, Al[ks][0], Al[ks][1], Al[ks][2], Al[ks][3], bh0, bh1);
        }
        int u0 = un0 + 2 * tig, u1 = u0 + 1;
        float ci0 = smf[T2_C1 / 4 + u0],       ci1 = smf[T2_C1 / 4 + u1];
        float cg0 = smf[T2_C1 / 4 + 64 + u0],  cg1 = smf[T2_C1 / 4 + 64 + u1];
        float co0 = smf[T2_C1 / 4 + 128 + u0], co1 = smf[T2_C1 / 4 + 128 + u1];
        float wm0 = smf[T2_WMU / 4 + u0], wm1 = smf[T2_WMU / 4 + u1];
        float ws0 = smf[T2_WSG / 4 + u0], ws1 = smf[T2_WSG / 4 + u1];
        // row r0+g (d[0], d[1])
        {
            float c0 = sigapx(di[0] + ci0) * tanhapx(dg[0] + cg0);
            float h0 = fmaxf(sigapx(dq[0] + co0) * tanhapx(c0), 0.f);
            float c1 = sigapx(di[1] + ci1) * tanhapx(dg[1] + cg1);
            float h1 = fmaxf(sigapx(dq[1] + co1) * tanhapx(c1), 0.f);
            muA = fmaf(h0, wm0, muA); muA = fmaf(h1, wm1, muA);
            sgA = fmaf(h0, ws0, sgA); sgA = fmaf(h1, ws1, sgA);
        }
        // row r0+g+8 (d[2], d[3])
        {
            float c0 = sigapx(di[2] + ci0) * tanhapx(dg[2] + cg0);
            float h0 = fmaxf(sigapx(dq[2] + co0) * tanhapx(c0), 0.f);
            float c1 = sigapx(di[3] + ci1) * tanhapx(dg[3] + cg1);
            float h1 = fmaxf(sigapx(dq[3] + co1) * tanhapx(c1), 0.f);
            muB = fmaf(h0, wm0, muB); muB = fmaf(h1, wm1, muB);
            sgB = fmaf(h0, ws0, sgB); sgB = fmaf(h1, ws1, sgB);
        }
    }

    // reduce over the 4-lane tig group
    muA += __shfl_xor_sync(0xffffffffu, muA, 1);
    muA += __shfl_xor_sync(0xffffffffu, muA, 2);
    sgA += __shfl_xor_sync(0xffffffffu, sgA, 1);
    sgA += __shfl_xor_sync(0xffffffffu, sgA, 2);
    muB += __shfl_xor_sync(0xffffffffu, muB, 1);
    muB += __shfl_xor_sync(0xffffffffu, muB, 2);
    sgB += __shfl_xor_sync(0xffffffffu, sgB, 1);
    sgB += __shfl_xor_sync(0xffffffffu, sgB, 2);

    // lanes tig==0 and tig==1 write rows r0+g and r0+g+8 respectively
    if (tig < 2) {
        int row = r0 + g + (tig ? 8 : 0);
        float mu = (tig ? muB : muA) + b_mu[0];
        float sg = (tig ? sgB : sgA) + b_sigma[0];
        int grow = rowbase + row;
        int n = grow / SEQL, t = grow - n * SEQL;
        float sigma = fsoftplus(sg) + 1e-6f;
        out_mu[n * TT + t] = mu;
        out_sg[n * TT + t] = sigma;
        if (t == SEQL - 1) {
            float yn = y[grow];
            float inv = __fdividef(1.f, sigma);
            float dd = yn - mu;
            float lik = 0.3989422804014327f * inv * __expf(-0.5f * dd * dd * inv * inv);
            out_yp[n * HOR] = lik;
            g_carry[n] = lik;
        }
    }
}

// =============================================================================
// kB: 24-step recurrence (unchanged)
#define SMB_WJ  0
#define SMB_V   12288
#define SMB_C1  12480
#define SMB_WMU 12672
#define SMB_WSG 12736
#define SMB_H1  12800
#define SMB_PMU 14912
#define SMB_PSG 15440
#define SMB_YN  15968
#define SMB_FLOATS 16000
#define SMB_BYTES (SMB_FLOATS * 4)

__global__ void __launch_bounds__(512) kB(
    const float* __restrict__ W_ih, const float* __restrict__ b_ih,
    const float* __restrict__ b_hh, const float* __restrict__ W_embed,
    const float* __restrict__ b_embed, const float* __restrict__ W_mu,
    const float* __restrict__ b_mu, const float* __restrict__ W_sigma,
    const float* __restrict__ b_sigma,
    float* __restrict__ out_yp, float* __restrict__ out_mu,
    float* __restrict__ out_sg)
{
    extern __shared__ float sm[];
    int tid = threadIdx.x;
    for (int i = tid; i < 12288; i += 512) {
        int g = i >> 12, u = (i >> 6) & 63, k = i & 63;
        sm[SMB_WJ + (g * 64 + u) * 64 + k] = W_ih[16384 + rowsel(g, u) * 64 + k];
    }
    for (int j = tid; j < 192; j += 512) {
        int g = j >> 6, u = j & 63, row = rowsel(g, u);
        float v = 0.f;
        #pragma unroll
        for (int e = 0; e < 32; e++)
            v = fmaf(W_ih[row * 64 + 32 + e], W_embed[e], v);
        sm[SMB_V + j] = v;
        sm[SMB_C1 + j] = b_ih[256 + row] + b_hh[256 + row];
    }
    for (int i = tid; i < 64; i += 512) {
        sm[SMB_WMU + i] = W_mu[i];
        sm[SMB_WSG + i] = W_sigma[i];
    }
    __syncthreads();

    int w = tid >> 5, s = tid & 31;
    int n = blockIdx.x * 32 + s, ub = w * 4;
    float yn = g_carry[n];
    float bmu = b_mu[0], bsg = b_sigma[0];

    #pragma unroll 1
    for (int t = SEQL; t < TT; t++) {
        int tp = t - SEQL;
        const float* gx = g_Gx + (size_t)tp * 192 * 4096 + n;
        #pragma unroll
        for (int j = 0; j < 4; j++) {
            int uu = ub + j;
            float ai = fmaf(yn, sm[SMB_V + uu], gx[uu * 4096]);
            float ag = fmaf(yn, sm[SMB_V + 64 + uu], gx[(64 + uu) * 4096]);
            float ao = fmaf(yn, sm[SMB_V + 128 + uu], gx[(128 + uu) * 4096]);
            float c = sigapx(ai) * tanhapx(ag);
            sm[SMB_H1 + s * 66 + uu] = sigapx(ao) * tanhapx(c);
        }
        __syncthreads();
        u64 hp[32];
        #pragma unroll
        for (int k2 = 0; k2 < 32; k2++)
            hp[k2] = *(const u64*)&sm[SMB_H1 + s * 66 + 2 * k2];
        float pmu = 0.f, psg = 0.f;
        #pragma unroll
        for (int j = 0; j < 4; j++) {
            int uu = ub + j;
            u64 ai2 = pack2(sm[SMB_C1 + uu], 0.f);
            u64 ag2 = pack2(sm[SMB_C1 + 64 + uu], 0.f);
            u64 ao2 = pack2(sm[SMB_C1 + 128 + uu], 0.f);
            const ulonglong2* wiv = (const ulonglong2*)&sm[SMB_WJ + uu * 64];
            const ulonglong2* wgv = (const ulonglong2*)&sm[SMB_WJ + (64 + uu) * 64];
            const ulonglong2* wov = (const ulonglong2*)&sm[SMB_WJ + (128 + uu) * 64];
            #pragma unroll
            for (int k4 = 0; k4 < 16; k4++) {
                ulonglong2 a = wiv[k4], b = wgv[k4], cw = wov[k4];
                u64 h0 = hp[2 * k4], h1v = hp[2 * k4 + 1];
                ai2 = ffma2(h0, a.x, ai2);  ai2 = ffma2(h1v, a.y, ai2);
                ag2 = ffma2(h0, b.x, ag2);  ag2 = ffma2(h1v, b.y, ag2);
                ao2 = ffma2(h0, cw.x, ao2); ao2 = ffma2(h1v, cw.y, ao2);
            }
            float al, ah, gl, gh, ol, oh;
            unpack2(ai2, al, ah); unpack2(ag2, gl, gh); unpack2(ao2, ol, oh);
            float ai = al + ah, ag = gl + gh, ao = ol + oh;
            float c = sigapx(ai) * tanhapx(ag);
            float h2 = fmaxf(sigapx(ao) * tanhapx(c), 0.f);
            pmu = fmaf(h2, sm[SMB_WMU + uu], pmu);
            psg = fmaf(h2, sm[SMB_WSG + uu], psg);
        }
        sm[SMB_PMU + w * 33 + s] = pmu;
        sm[SMB_PSG + w * 33 + s] = psg;
        __syncthreads();
        if (tid < 32) {
            float mu = bmu, sg = bsg;
            #pragma unroll
            for (int w2 = 0; w2 < 16; w2++) {
                mu += sm[SMB_PMU + w2 * 33 + s];
                sg += sm[SMB_PSG + w2 * 33 + s];
            }
            float sigma = fsoftplus(sg) + 1e-6f;
            out_mu[n * TT + t] = mu;
            out_sg[n * TT + t] = sigma;
            float inv = __fdividef(1.f, sigma);
            float d = yn - mu;
            float lik = 0.3989422804014327f * inv * __expf(-0.5f * d * d * inv * inv);
            if (t < TT - 1) out_yp[n * HOR + tp + 1] = lik;
            sm[SMB_YN + s] = lik;
        }
        __syncthreads();
        yn = sm[SMB_YN + s];
    }
}

// =============================================================================
extern "C" void kernel_launch(void* const* d_in, const int* in_sizes, int n_in,
                              void* d_out, int out_size)
{
    (void)in_sizes; (void)n_in;
    const float* X       = (const float*)d_in[0];
    const float* y       = (const float*)d_in[1];
    const float* Xf      = (const float*)d_in[2];
    const float* W_embed = (const float*)d_in[3];
    const float* b_embed = (const float*)d_in[4];
    const float* W_ih    = (const float*)d_in[5];
    const float* b_ih    = (const float*)d_in[6];
    const float* b_hh    = (const float*)d_in[7];
    const float* W_mu    = (const float*)d_in[8];
    const float* b_mu    = (const float*)d_in[9];
    const float* W_sigma = (const float*)d_in[10];
    const float* b_sigma = (const float*)d_in[11];

    float* out = (float*)d_out;
    float* yp = out;
    float* omu;
    float* osg;
    const int full = NTS * HOR + 2 * NTS * TT;
    if (out_size >= full) {
        omu = out + NTS * HOR;
        osg = omu + NTS * TT;
    } else {
        void* p0; void* p1;
        cudaGetSymbolAddress(&p0, g_mu_fb);
        cudaGetSymbolAddress(&p1, g_sg_fb);
        omu = (float*)p0; osg = (float*)p1;
    }

    cudaFuncSetAttribute(kP1a,  cudaFuncAttributeMaxDynamicSharedMemorySize, SMA_BYTES);
    cudaFuncSetAttribute(kP1b,  cudaFuncAttributeMaxDynamicSharedMemorySize, SMA_BYTES);
    cudaFuncSetAttribute(kP2tc, cudaFuncAttributeMaxDynamicSharedMemorySize, T2_BYTES);
    cudaFuncSetAttribute(kB,    cudaFuncAttributeMaxDynamicSharedMemorySize, SMB_BYTES);

    kPrepB<<<(192 * 64 + 255) / 256, 256>>>(W_ih);
    kP1a<<<TR / 128, 256, SMA_BYTES>>>(X, y, W_ih, b_ih, b_hh, W_embed, b_embed);
    kP1b<<<dim3(NTS / 128, HOR), 256, SMA_BYTES>>>(Xf, W_ih, b_ih, b_hh, b_embed);
    kP2tc<<<TR / 128, 256, T2_BYTES>>>(b_ih, b_hh, W_mu, b_mu, W_sigma,
                                       b_sigma, y, yp, omu, osg);
    kB<<<NTS / 32, 512, SMB_BYTES>>>(W_ih, b_ih, b_hh, W_embed, b_embed,
                                     W_mu, b_mu, W_sigma, b_sigma, yp, omu, osg);
}

// round 16
// speedup vs baseline: 1.7217x; 1.7217x over previous
#include <cuda_runtime.h>
#include <cuda_bf16.h>
#include <cstdint>

#define NTS  4096
#define SEQL 168
#define HOR  24
#define TT   192
#define TR   (NTS*SEQL)   // 688128 teacher rows
#define FR   (NTS*HOR)    // 98304 forecast rows

typedef unsigned long long u64;
typedef unsigned int u32;

// ---- device scratch ----------------------------------------------------------
__device__ float g_h1[(size_t)TR * 64];         // [row][u] fp32
__device__ float g_Gx[(size_t)HOR * 192 * NTS]; // [tp][j][n]
__device__ float g_carry[NTS];
__device__ float g_mu_fb[NTS * TT];
__device__ float g_sg_fb[NTS * TT];
// pre-split planar weight images (gate-major j = 0..191)
__device__ __nv_bfloat16 g_Bhi[192 * 64];   // W1 [j][k0..63]
__device__ __nv_bfloat16 g_Blo[192 * 64];
__device__ __nv_bfloat16 g_B0hi[192 * 32];  // Wx [j][k0..31]
__device__ __nv_bfloat16 g_B0lo[192 * 32];

__device__ __forceinline__ int rowsel(int g, int u) {
    // torch gate rows: i=[0,64) f=[64,128) g=[128,192) o=[192,256); f skipped
    return (g == 0) ? u : ((g == 1) ? 128 + u : 192 + u);
}
__device__ __forceinline__ float tanhapx(float x) {
    float r; asm("tanh.approx.f32 %0, %1;" : "=f"(r) : "f"(x)); return r;
}
__device__ __forceinline__ float sigapx(float x) {
    return fmaf(0.5f, tanhapx(0.5f * x), 0.5f);
}
__device__ __forceinline__ float fsoftplus(float x) {
    return (x > 15.f) ? x : __logf(1.f + __expf(x));
}

// ---- packed f32x2 helpers (kB / kP1b) ----------------------------------------
__device__ __forceinline__ u64 pack2(float lo, float hi) {
    u64 r; asm("mov.b64 %0, {%1, %2};" : "=l"(r) : "f"(lo), "f"(hi)); return r;
}
__device__ __forceinline__ void unpack2(u64 v, float& lo, float& hi) {
    asm("mov.b64 {%0, %1}, %2;" : "=f"(lo), "=f"(hi) : "l"(v));
}
__device__ __forceinline__ u64 ffma2(u64 a, u64 b, u64 c) {
    u64 d; asm("fma.rn.f32x2 %0, %1, %2, %3;" : "=l"(d) : "l"(a), "l"(b), "l"(c));
    return d;
}

// ---- warp-level bf16 MMA (sm_80 base feature; legal at target sm_103) --------
__device__ __forceinline__ void mma_bf16(float d[4], u32 a0, u32 a1, u32 a2,
                                         u32 a3, u32 b0, u32 b1) {
    asm volatile(
        "mma.sync.aligned.m16n8k16.row.col.f32.bf16.bf16.f32 "
        "{%0,%1,%2,%3}, {%4,%5,%6,%7}, {%8,%9}, {%0,%1,%2,%3};"
        : "+f"(d[0]), "+f"(d[1]), "+f"(d[2]), "+f"(d[3])
        : "r"(a0), "r"(a1), "r"(a2), "r"(a3), "r"(b0), "r"(b1));
}

// =============================================================================
// kPrepB: split W1 (64 k-cols) and Wx (32 k-cols) into bf16 hi/lo planar images
__global__ void kPrepB(const float* __restrict__ W_ih)
{
    int idx = blockIdx.x * 256 + threadIdx.x;
    if (idx < 192 * 64) {
        int j = idx >> 6, k = idx & 63;
        int row = rowsel(j >> 6, j & 63);
        float w = W_ih[16384 + row * 64 + k];
        __nv_bfloat16 hi = __float2bfloat16(w);
        g_Bhi[j * 64 + k] = hi;
        g_Blo[j * 64 + k] = __float2bfloat16(w - __bfloat162float(hi));
    } else if (idx < 192 * 96) {
        int i2 = idx - 192 * 64;
        int j = i2 >> 5, k = i2 & 31;
        int row = rowsel(j >> 6, j & 63);
        float w = W_ih[row * 64 + k];
        __nv_bfloat16 hi = __float2bfloat16(w);
        g_B0hi[j * 32 + k] = hi;
        g_B0lo[j * 32 + k] = __float2bfloat16(w - __bfloat162float(hi));
    }
}

// =============================================================================
// kP1atc: layer0 for teacher rows via bf16-split mma.sync, register epilogue.
// gates[128x192] = Xsplit @ Wx^T + yn·v + c0 ; h1 -> g_h1 (fp32)
// Block = 256 threads (8 warps), 128 rows; warp w owns rows [w*16, w*16+16).
// smem (bytes), A/B row pad = 40 bf16 (80 B -> conflict-free fragment loads):
#define T1_AHI  0                      // 128 x 40 bf16 = 10240
#define T1_ALO  10240
#define T1_BHI  20480                  // 192 x 40 bf16 = 15360
#define T1_BLO  35840
#define T1_Y    51200                  // 128 f32
#define T1_V    51712                  // 192 f32
#define T1_C0   52480                  // 192 f32
#define T1_BYTES (T1_C0 + 768 + 128)   // ~53.4 KB -> 2 blocks/SM

__global__ void __launch_bounds__(256, 2) kP1atc(
    const float* __restrict__ X, const float* __restrict__ y,
    const float* __restrict__ W_ih, const float* __restrict__ b_ih,
    const float* __restrict__ b_hh, const float* __restrict__ W_embed,
    const float* __restrict__ b_embed)
{
    extern __shared__ char smc[];
    float* smf = (float*)smc;
    int tid = threadIdx.x;
    int rowbase = blockIdx.x * 128;

    // stage A: X[128x32] fp32 -> bf16 hi/lo, pad-40 rows
    {
        const float* xg = X + (size_t)rowbase * 32;
        for (int i = tid; i < 4096; i += 256) {
            int r = i >> 5, k = i & 31;
            float v = xg[i];
            __nv_bfloat16 hi = __float2bfloat16(v);
            *(__nv_bfloat16*)(smc + T1_AHI + (r * 40 + k) * 2) = hi;
            *(__nv_bfloat16*)(smc + T1_ALO + (r * 40 + k) * 2) =
                __float2bfloat16(v - __bfloat162float(hi));
        }
    }
    // stage B: planar [192][32] -> pad-40 rows
    for (int i = tid; i < 6144; i += 256) {
        int j = i >> 5, k = i & 31;
        *(__nv_bfloat16*)(smc + T1_BHI + (j * 40 + k) * 2) = g_B0hi[i];
        *(__nv_bfloat16*)(smc + T1_BLO + (j * 40 + k) * 2) = g_B0lo[i];
    }
    // y values + rank-1 vector v + bias c0
    for (int i = tid; i < 128; i += 256) smf[T1_Y / 4 + i] = y[rowbase + i];
    for (int j = tid; j < 192; j += 256) {
        int g = j >> 6, u = j & 63, row = rowsel(g, u);
        float v = 0.f, cb = 0.f;
        #pragma unroll
        for (int e = 0; e < 32; e++) {
            float w = W_ih[row * 64 + 32 + e];
            v = fmaf(w, W_embed[e], v); cb = fmaf(w, b_embed[e], cb);
        }
        smf[T1_V / 4 + j] = v;
        smf[T1_C0 / 4 + j] = b_ih[row] + b_hh[row] + cb;
    }
    __syncthreads();

    int w = tid >> 5, lane = tid & 31;
    int g = lane >> 2, tig = lane & 3;
    int r0 = w * 16;

    // hoist A fragments for both k-steps (hi and lo)
    u32 Ah[2][4], Al[2][4];
    #pragma unroll
    for (int ks = 0; ks < 2; ks++) {
        int kb = ks * 16;
        int ra = r0 + g, rb = r0 + g + 8;
        Ah[ks][0] = *(const u32*)(smc + T1_AHI + (ra * 40 + kb + 2 * tig) * 2);
        Ah[ks][1] = *(const u32*)(smc + T1_AHI + (rb * 40 + kb + 2 * tig) * 2);
        Ah[ks][2] = *(const u32*)(smc + T1_AHI + (ra * 40 + kb + 8 + 2 * tig) * 2);
        Ah[ks][3] = *(const u32*)(smc + T1_AHI + (rb * 40 + kb + 8 + 2 * tig) * 2);
        Al[ks][0] = *(const u32*)(smc + T1_ALO + (ra * 40 + kb + 2 * tig) * 2);
        Al[ks][1] = *(const u32*)(smc + T1_ALO + (rb * 40 + kb + 2 * tig) * 2);
        Al[ks][2] = *(const u32*)(smc + T1_ALO + (ra * 40 + kb + 8 + 2 * tig) * 2);
        Al[ks][3] = *(const u32*)(smc + T1_ALO + (rb * 40 + kb + 8 + 2 * tig) * 2);
    }

    float ynA = smf[T1_Y / 4 + r0 + g];
    float ynB = smf[T1_Y / 4 + r0 + g + 8];

    #pragma unroll 1
    for (int un0 = 0; un0 < 64; un0 += 8) {
        float di[4] = {0.f, 0.f, 0.f, 0.f};
        float dg[4] = {0.f, 0.f, 0.f, 0.f};
        float dq[4] = {0.f, 0.f, 0.f, 0.f};
        int nbi = un0 + g, nbg = 64 + un0 + g, nbo = 128 + un0 + g;
        #pragma unroll
        for (int ks = 0; ks < 2; ks++) {
            int kb = ks * 16;
            u32 bh0, bh1, bl0, bl1;
            bh0 = *(const u32*)(smc + T1_BHI + (nbi * 40 + kb + 2 * tig) * 2);
            bh1 = *(const u32*)(smc + T1_BHI + (nbi * 40 + kb + 8 + 2 * tig) * 2);
            bl0 = *(const u32*)(smc + T1_BLO + (nbi * 40 + kb + 2 * tig) * 2);
            bl1 = *(const u32*)(smc + T1_BLO + (nbi * 40 + kb + 8 + 2 * tig) * 2);
            mma_bf16(di, Ah[ks][0], Ah[ks][1], Ah[ks][2], Ah[ks][3], bh0, bh1);
            mma_bf16(di, Ah[ks][0], Ah[ks][1], Ah[ks][2], Ah[ks][3], bl0, bl1);
            mma_bf16(di, Al[ks][0], Al[ks][1], Al[ks][2], Al[ks][3], bh0, bh1);
            bh0 = *(const u32*)(smc + T1_BHI + (nbg * 40 + kb + 2 * tig) * 2);
            bh1 = *(const u32*)(smc + T1_BHI + (nbg * 40 + kb + 8 + 2 * tig) * 2);
            bl0 = *(const u32*)(smc + T1_BLO + (nbg * 40 + kb + 2 * tig) * 2);
            bl1 = *(const u32*)(smc + T1_BLO + (nbg * 40 + kb + 8 + 2 * tig) * 2);
            mma_bf16(dg, Ah[ks][0], Ah[ks][1], Ah[ks][2], Ah[ks][3], bh0, bh1);
            mma_bf16(dg, Ah[ks][0], Ah[ks][1], Ah[ks][2], Ah[ks][3], bl0, bl1);
            mma_bf16(dg, Al[ks][0], Al[ks][1], Al[ks][2], Al[ks][3], bh0, bh1);
            bh0 = *(const u32*)(smc + T1_BHI + (nbo * 40 + kb + 2 * tig) * 2);
            bh1 = *(const u32*)(smc + T1_BHI + (nbo * 40 + kb + 8 + 2 * tig) * 2);
            bl0 = *(const u32*)(smc + T1_BLO + (nbo * 40 + kb + 2 * tig) * 2);
            bl1 = *(const u32*)(smc + T1_BLO + (nbo * 40 + kb + 8 + 2 * tig) * 2);
            mma_bf16(dq, Ah[ks][0], Ah[ks][1], Ah[ks][2], Ah[ks][3], bh0, bh1);
            mma_bf16(dq, Ah[ks][0], Ah[ks][1], Ah[ks][2], Ah[ks][3], bl0, bl1);
            mma_bf16(dq, Al[ks][0], Al[ks][1], Al[ks][2], Al[ks][3], bh0, bh1);
        }
        int u0 = un0 + 2 * tig, u1 = u0 + 1;
        float vi0 = smf[T1_V / 4 + u0],       vi1 = smf[T1_V / 4 + u1];
        float vg0 = smf[T1_V / 4 + 64 + u0],  vg1 = smf[T1_V / 4 + 64 + u1];
        float vo0 = smf[T1_V / 4 + 128 + u0], vo1 = smf[T1_V / 4 + 128 + u1];
        float ci0 = smf[T1_C0 / 4 + u0],       ci1 = smf[T1_C0 / 4 + u1];
        float cg0 = smf[T1_C0 / 4 + 64 + u0],  cg1 = smf[T1_C0 / 4 + 64 + u1];
        float co0 = smf[T1_C0 / 4 + 128 + u0], co1 = smf[T1_C0 / 4 + 128 + u1];
        // row r0+g
        {
            float ai0 = di[0] + fmaf(ynA, vi0, ci0);
            float ag0 = dg[0] + fmaf(ynA, vg0, cg0);
            float ao0 = dq[0] + fmaf(ynA, vo0, co0);
            float ai1 = di[1] + fmaf(ynA, vi1, ci1);
            float ag1 = dg[1] + fmaf(ynA, vg1, cg1);
            float ao1 = dq[1] + fmaf(ynA, vo1, co1);
            float c0 = sigapx(ai0) * tanhapx(ag0);
            float c1 = sigapx(ai1) * tanhapx(ag1);
            size_t base = (size_t)(rowbase + r0 + g) * 64;
            g_h1[base + u0] = sigapx(ao0) * tanhapx(c0);
            g_h1[base + u1] = sigapx(ao1) * tanhapx(c1);
        }
        // row r0+g+8
        {
            float ai0 = di[2] + fmaf(ynB, vi0, ci0);
            float ag0 = dg[2] + fmaf(ynB, vg0, cg0);
            float ao0 = dq[2] + fmaf(ynB, vo0, co0);
            float ai1 = di[3] + fmaf(ynB, vi1, ci1);
            float ag1 = dg[3] + fmaf(ynB, vg1, cg1);
            float ao1 = dq[3] + fmaf(ynB, vo1, co1);
            float c0 = sigapx(ai0) * tanhapx(ag0);
            float c1 = sigapx(ai1) * tanhapx(ag1);
            size_t base = (size_t)(rowbase + r0 + g + 8) * 64;
            g_h1[base + u0] = sigapx(ao0) * tanhapx(c0);
            g_h1[base + u1] = sigapx(ao1) * tanhapx(c1);
        }
    }
}

// =============================================================================
// P1b: layer0 x-part for forecast rows (FFMA2 path, unchanged)
#define SMA_W   0
#define SMA_X   6176
#define SMA_V   10528
#define SMA_C0  10720
#define SMA_FLOATS 10912
#define SMA_BYTES (SMA_FLOATS * 4)

#define GATE_FFMA2_16(wi2, wg2, wo2, xa, xb, xc, xd)                      \
    ai2[0]=ffma2(wi2, xa.x, ai2[0]); ai2[1]=ffma2(wi2, xa.y, ai2[1]);     \
    ai2[2]=ffma2(wi2, xb.x, ai2[2]); ai2[3]=ffma2(wi2, xb.y, ai2[3]);     \
    ai2[4]=ffma2(wi2, xc.x, ai2[4]); ai2[5]=ffma2(wi2, xc.y, ai2[5]);     \
    ai2[6]=ffma2(wi2, xd.x, ai2[6]); ai2[7]=ffma2(wi2, xd.y, ai2[7]);     \
    ag2[0]=ffma2(wg2, xa.x, ag2[0]); ag2[1]=ffma2(wg2, xa.y, ag2[1]);     \
    ag2[2]=ffma2(wg2, xb.x, ag2[2]); ag2[3]=ffma2(wg2, xb.y, ag2[3]);     \
    ag2[4]=ffma2(wg2, xc.x, ag2[4]); ag2[5]=ffma2(wg2, xc.y, ag2[5]);     \
    ag2[6]=ffma2(wg2, xd.x, ag2[6]); ag2[7]=ffma2(wg2, xd.y, ag2[7]);     \
    ao2[0]=ffma2(wo2, xa.x, ao2[0]); ao2[1]=ffma2(wo2, xa.y, ao2[1]);     \
    ao2[2]=ffma2(wo2, xb.x, ao2[2]); ao2[3]=ffma2(wo2, xb.y, ao2[3]);     \
    ao2[4]=ffma2(wo2, xc.x, ao2[4]); ao2[5]=ffma2(wo2, xc.y, ao2[5]);     \
    ao2[6]=ffma2(wo2, xd.x, ao2[6]); ao2[7]=ffma2(wo2, xd.y, ao2[7]);

__global__ void __launch_bounds__(256, 2) kP1b(
    const float* __restrict__ Xf,
    const float* __restrict__ W_ih, const float* __restrict__ b_ih,
    const float* __restrict__ b_hh, const float* __restrict__ b_embed)
{
    extern __shared__ float sm[];
    int tid = threadIdx.x;
    for (int i = tid; i < 6144; i += 256) {
        int g = i >> 11, u = (i >> 5) & 63, k = i & 31;
        sm[SMA_W + k * 193 + g * 64 + u] = W_ih[rowsel(g, u) * 64 + k];
    }
    for (int j = tid; j < 192; j += 256) {
        int g = j >> 6, u = j & 63, row = rowsel(g, u);
        float cb = 0.f;
        #pragma unroll
        for (int e = 0; e < 32; e++)
            cb = fmaf(W_ih[row * 64 + 32 + e], b_embed[e], cb);
        sm[SMA_C0 + j] = b_ih[row] + b_hh[row] + cb;
    }
    int tp = blockIdx.y, nbase = blockIdx.x * 128;
    for (int i = tid; i < 4096; i += 256) {
        int r = i >> 5, k = i & 31;
        sm[SMA_X + k * 132 + r] = Xf[((size_t)(nbase + r) * HOR + tp) * 32 + k];
    }
    __syncthreads();

    int u = tid & 63, rg = tid >> 6;
    float ci = sm[SMA_C0 + u], cg0 = sm[SMA_C0 + 64 + u], co = sm[SMA_C0 + 128 + u];

    #pragma unroll 1
    for (int rr = 0; rr < 2; rr++) {
        int r0 = rg * 32 + rr * 16;
        u64 ai2[8], ag2[8], ao2[8];
        #pragma unroll
        for (int p = 0; p < 8; p++) {
            ai2[p] = pack2(ci, ci);
            ag2[p] = pack2(cg0, cg0);
            ao2[p] = pack2(co, co);
        }
        #pragma unroll 4
        for (int k = 0; k < 32; k++) {
            float wi = sm[SMA_W + k * 193 + u];
            float wg = sm[SMA_W + k * 193 + 64 + u];
            float wo = sm[SMA_W + k * 193 + 128 + u];
            u64 wi2 = pack2(wi, wi), wg2 = pack2(wg, wg), wo2 = pack2(wo, wo);
            ulonglong2 xa = *(const ulonglong2*)&sm[SMA_X + k * 132 + r0];
            ulonglong2 xb = *(const ulonglong2*)&sm[SMA_X + k * 132 + r0 + 4];
            ulonglong2 xc = *(const ulonglong2*)&sm[SMA_X + k * 132 + r0 + 8];
            ulonglong2 xd = *(const ulonglong2*)&sm[SMA_X + k * 132 + r0 + 12];
            GATE_FFMA2_16(wi2, wg2, wo2, xa, xb, xc, xd)
        }
        u64* gi = (u64*)&g_Gx[((size_t)tp * 192 + u) * 4096 + nbase + r0];
        u64* gg = (u64*)&g_Gx[((size_t)tp * 192 + 64 + u) * 4096 + nbase + r0];
        u64* go = (u64*)&g_Gx[((size_t)tp * 192 + 128 + u) * 4096 + nbase + r0];
        #pragma unroll
        for (int p = 0; p < 4; p++) {
            *(ulonglong2*)(gi + 2 * p) = make_ulonglong2(ai2[2 * p], ai2[2 * p + 1]);
            *(ulonglong2*)(gg + 2 * p) = make_ulonglong2(ag2[2 * p], ag2[2 * p + 1]);
            *(ulonglong2*)(go + 2 * p) = make_ulonglong2(ao2[2 * p], ao2[2 * p + 1]);
        }
    }
}

// =============================================================================
// kP2tc: layer1 + head via bf16-split mma.sync, register epilogue.
// Stage converts fp32 g_h1 -> bf16 hi/lo in-kernel.
#define T2_AHI  0                      // 128 x 72 bf16 = 18432
#define T2_ALO  18432
#define T2_BHI  36864                  // 192 x 72 bf16 = 27648
#define T2_BLO  64512
#define T2_C1   92160                  // 192 f32
#define T2_WMU  (T2_C1 + 768)          // 64 f32
#define T2_WSG  (T2_WMU + 256)         // 64 f32
#define T2_BYTES (T2_WSG + 256 + 128)  // ~91.6 KB -> 2 blocks/SM

__global__ void __launch_bounds__(256, 2) kP2tc(
    const float* __restrict__ b_ih, const float* __restrict__ b_hh,
    const float* __restrict__ W_mu, const float* __restrict__ b_mu,
    const float* __restrict__ W_sigma, const float* __restrict__ b_sigma,
    const float* __restrict__ y,
    float* __restrict__ out_yp, float* __restrict__ out_mu,
    float* __restrict__ out_sg)
{
    extern __shared__ char smc[];
    float* smf = (float*)smc;
    int tid = threadIdx.x;
    int rowbase = blockIdx.x * 128;

    // stage A: g_h1 fp32 -> bf16 hi/lo, pad-72 rows
    {
        const float* hg = g_h1 + (size_t)rowbase * 64;
        for (int i = tid; i < 8192; i += 256) {
            int r = i >> 6, u = i & 63;
            float v = hg[i];
            __nv_bfloat16 hi = __float2bfloat16(v);
            *(__nv_bfloat16*)(smc + T2_AHI + (r * 72 + u) * 2) = hi;
            *(__nv_bfloat16*)(smc + T2_ALO + (r * 72 + u) * 2) =
                __float2bfloat16(v - __bfloat162float(hi));
        }
    }
    // stage B: planar [192][64] -> pad-72 rows
    {
        const u32* sh = (const u32*)g_Bhi;
        const u32* sl = (const u32*)g_Blo;
        for (int i = tid; i < 192 * 32; i += 256) {
            int j = i >> 5, kw = i & 31;
            *(u32*)(smc + T2_BHI + (j * 72 + kw * 2) * 2) = sh[i];
            *(u32*)(smc + T2_BLO + (j * 72 + kw * 2) * 2) = sl[i];
        }
    }
    for (int j = tid; j < 192; j += 256) {
        int row = rowsel(j >> 6, j & 63);
        smf[T2_C1 / 4 + j] = b_ih[256 + row] + b_hh[256 + row];
    }
    if (tid < 64) {
        smf[T2_WMU / 4 + tid] = W_mu[tid];
        smf[T2_WSG / 4 + tid] = W_sigma[tid];
    }
    __syncthreads();

    int w = tid >> 5, lane = tid & 31;
    int g = lane >> 2, tig = lane & 3;
    int r0 = w * 16;

    u32 Ah[4][4], Al[4][4];
    #pragma unroll
    for (int ks = 0; ks < 4; ks++) {
        int kb = ks * 16;
        int ra = r0 + g, rb = r0 + g + 8;
        Ah[ks][0] = *(const u32*)(smc + T2_AHI + (ra * 72 + kb + 2 * tig) * 2);
        Ah[ks][1] = *(const u32*)(smc + T2_AHI + (rb * 72 + kb + 2 * tig) * 2);
        Ah[ks][2] = *(const u32*)(smc + T2_AHI + (ra * 72 + kb + 8 + 2 * tig) * 2);
        Ah[ks][3] = *(const u32*)(smc + T2_AHI + (rb * 72 + kb + 8 + 2 * tig) * 2);
        Al[ks][0] = *(const u32*)(smc + T2_ALO + (ra * 72 + kb + 2 * tig) * 2);
        Al[ks][1] = *(const u32*)(smc + T2_ALO + (rb * 72 + kb + 2 * tig) * 2);
        Al[ks][2] = *(const u32*)(smc + T2_ALO + (ra * 72 + kb + 8 + 2 * tig) * 2);
        Al[ks][3] = *(const u32*)(smc + T2_ALO + (rb * 72 + kb + 8 + 2 * tig) * 2);
    }

    float muA = 0.f, sgA = 0.f, muB = 0.f, sgB = 0.f;
    #pragma unroll 1
    for (int un0 = 0; un0 < 64; un0 += 8) {
        float di[4] = {0.f, 0.f, 0.f, 0.f};
        float dg[4] = {0.f, 0.f, 0.f, 0.f};
        float dq[4] = {0.f, 0.f, 0.f, 0.f};
        int nbi = un0 + g, nbg = 64 + un0 + g, nbo = 128 + un0 + g;
        #pragma unroll
        for (int ks = 0; ks < 4; ks++) {
            int kb = ks * 16;
            u32 bh0, bh1, bl0, bl1;
            bh0 = *(const u32*)(smc + T2_BHI + (nbi * 72 + kb + 2 * tig) * 2);
            bh1 = *(const u32*)(smc + T2_BHI + (nbi * 72 + kb + 8 + 2 * tig) * 2);
            bl0 = *(const u32*)(smc + T2_BLO + (nbi * 72 + kb + 2 * tig) * 2);
            bl1 = *(const u32*)(smc + T2_BLO + (nbi * 72 + kb + 8 + 2 * tig) * 2);
            mma_bf16(di, Ah[ks][0], Ah[ks][1], Ah[ks][2], Ah[ks][3], bh0, bh1);
            mma_bf16(di, Ah[ks][0], Ah[ks][1], Ah[ks][2], Ah[ks][3], bl0, bl1);
            mma_bf16(di, Al[ks][0], Al[ks][1], Al[ks][2], Al[ks][3], bh0, bh1);
            bh0 = *(const u32*)(smc + T2_BHI + (nbg * 72 + kb + 2 * tig) * 2);
            bh1 = *(const u32*)(smc + T2_BHI + (nbg * 72 + kb + 8 + 2 * tig) * 2);
            bl0 = *(const u32*)(smc + T2_BLO + (nbg * 72 + kb + 2 * tig) * 2);
            bl1 = *(const u32*)(smc + T2_BLO + (nbg * 72 + kb + 8 + 2 * tig) * 2);
            mma_bf16(dg, Ah[ks][0], Ah[ks][1], Ah[ks][2], Ah[ks][3], bh0, bh1);
            mma_bf16(dg, Ah[ks][0], Ah[ks][1], Ah[ks][2], Ah[ks][3], bl0, bl1);
            mma_bf16(dg, Al[ks][0], Al[ks][1], Al[ks][2], Al[ks][3], bh0, bh1);
            bh0 = *(const u32*)(smc + T2_BHI + (nbo * 72 + kb + 2 * tig) * 2);
            bh1 = *(const u32*)(smc + T2_BHI + (nbo * 72 + kb + 8 + 2 * tig) * 2);
            bl0 = *(const u32*)(smc + T2_BLO + (nbo * 72 + kb + 2 * tig) * 2);
            bl1 = *(const u32*)(smc + T2_BLO + (nbo * 72 + kb + 8 + 2 * tig) * 2);
            mma_bf16(dq, Ah[ks][0], Ah[ks][1], Ah[ks][2], Ah[ks][3], bh0, bh1);
            mma_bf16(dq, Ah[ks][0], Ah[ks][1], Ah[ks][2], Ah[ks][3], bl0, bl1);
            mma_bf16(dq, Al[ks][0], Al[ks][1], Al[ks][2], Al[ks][3], bh0, bh1);
        }
        int u0 = un0 + 2 * tig, u1 = u0 + 1;
        float ci0 = smf[T2_C1 / 4 + u0],       ci1 = smf[T2_C1 / 4 + u1];
        float cg0 = smf[T2_C1 / 4 + 64 + u0],  cg1 = smf[T2_C1 / 4 + 64 + u1];
        float co0 = smf[T2_C1 / 4 + 128 + u0], co1 = smf[T2_C1 / 4 + 128 + u1];
        float wm0 = smf[T2_WMU / 4 + u0], wm1 = smf[T2_WMU / 4 + u1];
        float ws0 = smf[T2_WSG / 4 + u0], ws1 = smf[T2_WSG / 4 + u1];
        {
            float c0 = sigapx(di[0] + ci0) * tanhapx(dg[0] + cg0);
            float h0 = fmaxf(sigapx(dq[0] + co0) * tanhapx(c0), 0.f);
            float c1 = sigapx(di[1] + ci1) * tanhapx(dg[1] + cg1);
            float h1 = fmaxf(sigapx(dq[1] + co1) * tanhapx(c1), 0.f);
            muA = fmaf(h0, wm0, muA); muA = fmaf(h1, wm1, muA);
            sgA = fmaf(h0, ws0, sgA); sgA = fmaf(h1, ws1, sgA);
        }
        {
            float c0 = sigapx(di[2] + ci0) * tanhapx(dg[2] + cg0);
            float h0 = fmaxf(sigapx(dq[2] + co0) * tanhapx(c0), 0.f);
            float c1 = sigapx(di[3] + ci1) * tanhapx(dg[3] + cg1);
            float h1 = fmaxf(sigapx(dq[3] + co1) * tanhapx(c1), 0.f);
            muB = fmaf(h0, wm0, muB); muB = fmaf(h1, wm1, muB);
            sgB = fmaf(h0, ws0, sgB); sgB = fmaf(h1, ws1, sgB);
        }
    }

    muA += __shfl_xor_sync(0xffffffffu, muA, 1);
    muA += __shfl_xor_sync(0xffffffffu, muA, 2);
    sgA += __shfl_xor_sync(0xffffffffu, sgA, 1);
    sgA += __shfl_xor_sync(0xffffffffu, sgA, 2);
    muB += __shfl_xor_sync(0xffffffffu, muB, 1);
    muB += __shfl_xor_sync(0xffffffffu, muB, 2);
    sgB += __shfl_xor_sync(0xffffffffu, sgB, 1);
    sgB += __shfl_xor_sync(0xffffffffu, sgB, 2);

    if (tig < 2) {
        int row = r0 + g + (tig ? 8 : 0);
        float mu = (tig ? muB : muA) + b_mu[0];
        float sg = (tig ? sgB : sgA) + b_sigma[0];
        int grow = rowbase + row;
        int n = grow / SEQL, t = grow - n * SEQL;
        float sigma = fsoftplus(sg) + 1e-6f;
        out_mu[n * TT + t] = mu;
        out_sg[n * TT + t] = sigma;
        if (t == SEQL - 1) {
            float yn = y[grow];
            float inv = __fdividef(1.f, sigma);
            float dd = yn - mu;
            float lik = 0.3989422804014327f * inv * __expf(-0.5f * dd * dd * inv * inv);
            out_yp[n * HOR] = lik;
            g_carry[n] = lik;
        }
    }
}

// =============================================================================
// kB: 24-step recurrence (unchanged)
#define SMB_WJ  0
#define SMB_V   12288
#define SMB_C1  12480
#define SMB_WMU 12672
#define SMB_WSG 12736
#define SMB_H1  12800
#define SMB_PMU 14912
#define SMB_PSG 15440
#define SMB_YN  15968
#define SMB_FLOATS 16000
#define SMB_BYTES (SMB_FLOATS * 4)

__global__ void __launch_bounds__(512) kB(
    const float* __restrict__ W_ih, const float* __restrict__ b_ih,
    const float* __restrict__ b_hh, const float* __restrict__ W_embed,
    const float* __restrict__ b_embed, const float* __restrict__ W_mu,
    const float* __restrict__ b_mu, const float* __restrict__ W_sigma,
    const float* __restrict__ b_sigma,
    float* __restrict__ out_yp, float* __restrict__ out_mu,
    float* __restrict__ out_sg)
{
    extern __shared__ float sm[];
    int tid = threadIdx.x;
    for (int i = tid; i < 12288; i += 512) {
        int g = i >> 12, u = (i >> 6) & 63, k = i & 63;
        sm[SMB_WJ + (g * 64 + u) * 64 + k] = W_ih[16384 + rowsel(g, u) * 64 + k];
    }
    for (int j = tid; j < 192; j += 512) {
        int g = j >> 6, u = j & 63, row = rowsel(g, u);
        float v = 0.f;
        #pragma unroll
        for (int e = 0; e < 32; e++)
            v = fmaf(W_ih[row * 64 + 32 + e], W_embed[e], v);
        sm[SMB_V + j] = v;
        sm[SMB_C1 + j] = b_ih[256 + row] + b_hh[256 + row];
    }
    for (int i = tid; i < 64; i += 512) {
        sm[SMB_WMU + i] = W_mu[i];
        sm[SMB_WSG + i] = W_sigma[i];
    }
    __syncthreads();

    int w = tid >> 5, s = tid & 31;
    int n = blockIdx.x * 32 + s, ub = w * 4;
    float yn = g_carry[n];
    float bmu = b_mu[0], bsg = b_sigma[0];

    #pragma unroll 1
    for (int t = SEQL; t < TT; t++) {
        int tp = t - SEQL;
        const float* gx = g_Gx + (size_t)tp * 192 * 4096 + n;
        #pragma unroll
        for (int j = 0; j < 4; j++) {
            int uu = ub + j;
            float ai = fmaf(yn, sm[SMB_V + uu], gx[uu * 4096]);
            float ag = fmaf(yn, sm[SMB_V + 64 + uu], gx[(64 + uu) * 4096]);
            float ao = fmaf(yn, sm[SMB_V + 128 + uu], gx[(128 + uu) * 4096]);
            float c = sigapx(ai) * tanhapx(ag);
            sm[SMB_H1 + s * 66 + uu] = sigapx(ao) * tanhapx(c);
        }
        __syncthreads();
        u64 hp[32];
        #pragma unroll
        for (int k2 = 0; k2 < 32; k2++)
            hp[k2] = *(const u64*)&sm[SMB_H1 + s * 66 + 2 * k2];
        float pmu = 0.f, psg = 0.f;
        #pragma unroll
        for (int j = 0; j < 4; j++) {
            int uu = ub + j;
            u64 ai2 = pack2(sm[SMB_C1 + uu], 0.f);
            u64 ag2 = pack2(sm[SMB_C1 + 64 + uu], 0.f);
            u64 ao2 = pack2(sm[SMB_C1 + 128 + uu], 0.f);
            const ulonglong2* wiv = (const ulonglong2*)&sm[SMB_WJ + uu * 64];
            const ulonglong2* wgv = (const ulonglong2*)&sm[SMB_WJ + (64 + uu) * 64];
            const ulonglong2* wov = (const ulonglong2*)&sm[SMB_WJ + (128 + uu) * 64];
            #pragma unroll
            for (int k4 = 0; k4 < 16; k4++) {
                ulonglong2 a = wiv[k4], b = wgv[k4], cw = wov[k4];
                u64 h0 = hp[2 * k4], h1v = hp[2 * k4 + 1];
                ai2 = ffma2(h0, a.x, ai2);  ai2 = ffma2(h1v, a.y, ai2);
                ag2 = ffma2(h0, b.x, ag2);  ag2 = ffma2(h1v, b.y, ag2);
                ao2 = ffma2(h0, cw.x, ao2); ao2 = ffma2(h1v, cw.y, ao2);
            }
            float al, ah, gl, gh, ol, oh;
            unpack2(ai2, al, ah); unpack2(ag2, gl, gh); unpack2(ao2, ol, oh);
            float ai = al + ah, ag = gl + gh, ao = ol + oh;
            float c = sigapx(ai) * tanhapx(ag);
            float h2 = fmaxf(sigapx(ao) * tanhapx(c), 0.f);
            pmu = fmaf(h2, sm[SMB_WMU + uu], pmu);
            psg = fmaf(h2, sm[SMB_WSG + uu], psg);
        }
        sm[SMB_PMU + w * 33 + s] = pmu;
        sm[SMB_PSG + w * 33 + s] = psg;
        __syncthreads();
        if (tid < 32) {
            float mu = bmu, sg = bsg;
            #pragma unroll
            for (int w2 = 0; w2 < 16; w2++) {
                mu += sm[SMB_PMU + w2 * 33 + s];
                sg += sm[SMB_PSG + w2 * 33 + s];
            }
            float sigma = fsoftplus(sg) + 1e-6f;
            out_mu[n * TT + t] = mu;
            out_sg[n * TT + t] = sigma;
            float inv = __fdividef(1.f, sigma);
            float d = yn - mu;
            float lik = 0.3989422804014327f * inv * __expf(-0.5f * d * d * inv * inv);
            if (t < TT - 1) out_yp[n * HOR + tp + 1] = lik;
            sm[SMB_YN + s] = lik;
        }
        __syncthreads();
        yn = sm[SMB_YN + s];
    }
}

// =============================================================================
extern "C" void kernel_launch(void* const* d_in, const int* in_sizes, int n_in,
                              void* d_out, int out_size)
{
    (void)in_sizes; (void)n_in;
    const float* X       = (const float*)d_in[0];
    const float* y       = (const float*)d_in[1];
    const float* Xf      = (const float*)d_in[2];
    const float* W_embed = (const float*)d_in[3];
    const float* b_embed = (const float*)d_in[4];
    const float* W_ih    = (const float*)d_in[5];
    const float* b_ih    = (const float*)d_in[6];
    const float* b_hh    = (const float*)d_in[7];
    const float* W_mu    = (const float*)d_in[8];
    const float* b_mu    = (const float*)d_in[9];
    const float* W_sigma = (const float*)d_in[10];
    const float* b_sigma = (const float*)d_in[11];

    float* out = (float*)d_out;
    float* yp = out;
    float* omu;
    float* osg;
    const int full = NTS * HOR + 2 * NTS * TT;
    if (out_size >= full) {
        omu = out + NTS * HOR;
        osg = omu + NTS * TT;
    } else {
        void* p0; void* p1;
        cudaGetSymbolAddress(&p0, g_mu_fb);
        cudaGetSymbolAddress(&p1, g_sg_fb);
        omu = (float*)p0; osg = (float*)p1;
    }

    cudaFuncSetAttribute(kP1atc, cudaFuncAttributeMaxDynamicSharedMemorySize, T1_BYTES);
    cudaFuncSetAttribute(kP1b,   cudaFuncAttributeMaxDynamicSharedMemorySize, SMA_BYTES);
    cudaFuncSetAttribute(kP2tc,  cudaFuncAttributeMaxDynamicSharedMemorySize, T2_BYTES);
    cudaFuncSetAttribute(kB,     cudaFuncAttributeMaxDynamicSharedMemorySize, SMB_BYTES);

    kPrepB<<<(192 * 96 + 255) / 256, 256>>>(W_ih);
    kP1atc<<<TR / 128, 256, T1_BYTES>>>(X, y, W_ih, b_ih, b_hh, W_embed, b_embed);
    kP1b<<<dim3(NTS / 128, HOR), 256, SMA_BYTES>>>(Xf, W_ih, b_ih, b_hh, b_embed);
    kP2tc<<<TR / 128, 256, T2_BYTES>>>(b_ih, b_hh, W_mu, b_mu, W_sigma,
                                       b_sigma, y, yp, omu, osg);
    kB<<<NTS / 32, 512, SMB_BYTES>>>(W_ih, b_ih, b_hh, W_embed, b_embed,
                                     W_mu, b_mu, W_sigma, b_sigma, yp, omu, osg);
}

// round 17
// speedup vs baseline: 2.3455x; 1.3623x over previous
#include <cuda_runtime.h>
#include <cuda_bf16.h>
#include <cstdint>

#define NTS  4096
#define SEQL 168
#define HOR  24
#define TT   192
#define TR   (NTS*SEQL)   // 688128 teacher rows
#define FR   (NTS*HOR)    // 98304 forecast rows

typedef unsigned long long u64;
typedef unsigned int u32;

// ---- device scratch ----------------------------------------------------------
__device__ float g_Gx[(size_t)HOR * 192 * NTS]; // [tp][j][n]
__device__ float g_carry[NTS];
__device__ float g_mu_fb[NTS * TT];
__device__ float g_sg_fb[NTS * TT];
// pre-split planar weight images (gate-major j = 0..191)
__device__ __nv_bfloat16 g_Bhi[192 * 64];   // W1 [j][k0..63]
__device__ __nv_bfloat16 g_Blo[192 * 64];
__device__ __nv_bfloat16 g_B0hi[192 * 32];  // Wx [j][k0..31]
__device__ __nv_bfloat16 g_B0lo[192 * 32];
__device__ float g_V[192], g_C0[192], g_C1[192];

__device__ __forceinline__ int rowsel(int g, int u) {
    // torch gate rows: i=[0,64) f=[64,128) g=[128,192) o=[192,256); f skipped
    return (g == 0) ? u : ((g == 1) ? 128 + u : 192 + u);
}
__device__ __forceinline__ float tanhapx(float x) {
    float r; asm("tanh.approx.f32 %0, %1;" : "=f"(r) : "f"(x)); return r;
}
__device__ __forceinline__ float sigapx(float x) {
    return fmaf(0.5f, tanhapx(0.5f * x), 0.5f);
}
__device__ __forceinline__ float fsoftplus(float x) {
    return (x > 15.f) ? x : __logf(1.f + __expf(x));
}

// ---- packed f32x2 helpers (kB / kP1b) ----------------------------------------
__device__ __forceinline__ u64 pack2(float lo, float hi) {
    u64 r; asm("mov.b64 %0, {%1, %2};" : "=l"(r) : "f"(lo), "f"(hi)); return r;
}
__device__ __forceinline__ void unpack2(u64 v, float& lo, float& hi) {
    asm("mov.b64 {%0, %1}, %2;" : "=f"(lo), "=f"(hi) : "l"(v));
}
__device__ __forceinline__ u64 ffma2(u64 a, u64 b, u64 c) {
    u64 d; asm("fma.rn.f32x2 %0, %1, %2, %3;" : "=l"(d) : "l"(a), "l"(b), "l"(c));
    return d;
}

// ---- warp-level bf16 MMA -----------------------------------------------------
__device__ __forceinline__ void mma_bf16(float d[4], u32 a0, u32 a1, u32 a2,
                                         u32 a3, u32 b0, u32 b1) {
    asm volatile(
        "mma.sync.aligned.m16n8k16.row.col.f32.bf16.bf16.f32 "
        "{%0,%1,%2,%3}, {%4,%5,%6,%7}, {%8,%9}, {%0,%1,%2,%3};"
        : "+f"(d[0]), "+f"(d[1]), "+f"(d[2]), "+f"(d[3])
        : "r"(a0), "r"(a1), "r"(a2), "r"(a3), "r"(b0), "r"(b1));
}

__device__ __forceinline__ u32 pack_bf16x2(float a, float b) {
    __nv_bfloat16 ha = __float2bfloat16(a), hb = __float2bfloat16(b);
    return (u32)__bfloat16_as_ushort(ha) | ((u32)__bfloat16_as_ushort(hb) << 16);
}

// =============================================================================
// kPrepB: split W1/Wx into bf16 hi/lo planar images + precompute V/C0/C1
__global__ void kPrepB(const float* __restrict__ W_ih,
                       const float* __restrict__ W_embed,
                       const float* __restrict__ b_embed,
                       const float* __restrict__ b_ih,
                       const float* __restrict__ b_hh)
{
    int idx = blockIdx.x * 256 + threadIdx.x;
    if (idx < 192 * 64) {
        int j = idx >> 6, k = idx & 63;
        int row = rowsel(j >> 6, j & 63);
        float w = W_ih[16384 + row * 64 + k];
        __nv_bfloat16 hi = __float2bfloat16(w);
        g_Bhi[j * 64 + k] = hi;
        g_Blo[j * 64 + k] = __float2bfloat16(w - __bfloat162float(hi));
    } else if (idx < 192 * 96) {
        int i2 = idx - 192 * 64;
        int j = i2 >> 5, k = i2 & 31;
        int row = rowsel(j >> 6, j & 63);
        float w = W_ih[row * 64 + k];
        __nv_bfloat16 hi = __float2bfloat16(w);
        g_B0hi[j * 32 + k] = hi;
        g_B0lo[j * 32 + k] = __float2bfloat16(w - __bfloat162float(hi));
    } else if (idx < 192 * 96 + 192) {
        int j = idx - 192 * 96;
        int row = rowsel(j >> 6, j & 63);
        float v = 0.f, cb = 0.f;
        #pragma unroll
        for (int e = 0; e < 32; e++) {
            float w = W_ih[row * 64 + 32 + e];
            v = fmaf(w, W_embed[e], v); cb = fmaf(w, b_embed[e], cb);
        }
        g_V[j] = v;
        g_C0[j] = b_ih[row] + b_hh[row] + cb;
        g_C1[j] = b_ih[256 + row] + b_hh[256 + row];
    }
}

// =============================================================================
// kPf: FUSED layer0 + layer1 + head for teacher rows. No h1 global roundtrip.
// Block = 256 threads (8 warps), 128 rows; warp w owns rows [w*16, w*16+16).
// smem: phase1 {X hi/lo pad-40, B0 hi/lo pad-40} overlaps phase2 {A1 hi/lo pad-72}
#define F_XHI  0                       // 10240
#define F_XLO  10240                   // 10240
#define F_B0HI 20480                   // 15360
#define F_B0LO 35840                   // 15360  (phase1 region ends 51200)
#define F_A1HI 0                       // 18432  (phase2, overlaps phase1)
#define F_A1LO 18432                   // 18432  (ends 36864)
#define F_B1HI 51200                   // 27648
#define F_B1LO 78848                   // 27648  (ends 106496)
#define F_CON  106496                  // 832 floats = 3328 B
#define F_BYTES (106496 + 3328 + 128)  // ~107.3 KB -> 2 blocks/SM

__global__ void __launch_bounds__(256, 2) kPf(
    const float* __restrict__ X, const float* __restrict__ y,
    const float* __restrict__ W_mu, const float* __restrict__ b_mu,
    const float* __restrict__ W_sigma, const float* __restrict__ b_sigma,
    float* __restrict__ out_yp, float* __restrict__ out_mu,
    float* __restrict__ out_sg)
{
    extern __shared__ char smc[];
    float* smf = (float*)smc;
    int tid = threadIdx.x;
    int rowbase = blockIdx.x * 128;

    float* cY  = smf + F_CON / 4;
    float* cV  = cY + 128;
    float* cC0 = cY + 320;
    float* cC1 = cY + 512;
    float* cWM = cY + 704;
    float* cWS = cY + 768;

    // stage X -> bf16 hi/lo, pad-40
    {
        const float* xg = X + (size_t)rowbase * 32;
        for (int i = tid; i < 4096; i += 256) {
            int r = i >> 5, k = i & 31;
            float v = xg[i];
            __nv_bfloat16 hi = __float2bfloat16(v);
            *(__nv_bfloat16*)(smc + F_XHI + (r * 40 + k) * 2) = hi;
            *(__nv_bfloat16*)(smc + F_XLO + (r * 40 + k) * 2) =
                __float2bfloat16(v - __bfloat162float(hi));
        }
    }
    // stage B0 pad-40
    for (int i = tid; i < 6144; i += 256) {
        int j = i >> 5, k = i & 31;
        *(__nv_bfloat16*)(smc + F_B0HI + (j * 40 + k) * 2) = g_B0hi[i];
        *(__nv_bfloat16*)(smc + F_B0LO + (j * 40 + k) * 2) = g_B0lo[i];
    }
    // stage B1 pad-72 (u32 pairs)
    {
        const u32* sh = (const u32*)g_Bhi;
        const u32* sl = (const u32*)g_Blo;
        for (int i = tid; i < 6144; i += 256) {
            int j = i >> 5, kw = i & 31;
            *(u32*)(smc + F_B1HI + (j * 72 + kw * 2) * 2) = sh[i];
            *(u32*)(smc + F_B1LO + (j * 72 + kw * 2) * 2) = sl[i];
        }
    }
    // consts
    for (int i = tid; i < 128; i += 256) cY[i] = y[rowbase + i];
    for (int j = tid; j < 192; j += 256) {
        cV[j] = g_V[j]; cC0[j] = g_C0[j]; cC1[j] = g_C1[j];
    }
    if (tid < 64) { cWM[tid] = W_mu[tid]; cWS[tid] = W_sigma[tid]; }
    __syncthreads();

    int w = tid >> 5, lane = tid & 31;
    int g = lane >> 2, tig = lane & 3;
    int r0 = w * 16;
    float ynA = cY[r0 + g], ynB = cY[r0 + g + 8];

    // ---------------- Phase 1: layer0 MMA, h1 kept in registers ---------------
    float h1reg[32];
    {
        u32 Ah[2][4], Al[2][4];
        #pragma unroll
        for (int ks = 0; ks < 2; ks++) {
            int kb = ks * 16;
            int ra = r0 + g, rb = r0 + g + 8;
            Ah[ks][0] = *(const u32*)(smc + F_XHI + (ra * 40 + kb + 2 * tig) * 2);
            Ah[ks][1] = *(const u32*)(smc + F_XHI + (rb * 40 + kb + 2 * tig) * 2);
            Ah[ks][2] = *(const u32*)(smc + F_XHI + (ra * 40 + kb + 8 + 2 * tig) * 2);
            Ah[ks][3] = *(const u32*)(smc + F_XHI + (rb * 40 + kb + 8 + 2 * tig) * 2);
            Al[ks][0] = *(const u32*)(smc + F_XLO + (ra * 40 + kb + 2 * tig) * 2);
            Al[ks][1] = *(const u32*)(smc + F_XLO + (rb * 40 + kb + 2 * tig) * 2);
            Al[ks][2] = *(const u32*)(smc + F_XLO + (ra * 40 + kb + 8 + 2 * tig) * 2);
            Al[ks][3] = *(const u32*)(smc + F_XLO + (rb * 40 + kb + 8 + 2 * tig) * 2);
        }
        #pragma unroll 1
        for (int un0 = 0; un0 < 64; un0 += 8) {
            float di[4] = {0.f, 0.f, 0.f, 0.f};
            float dg[4] = {0.f, 0.f, 0.f, 0.f};
            float dq[4] = {0.f, 0.f, 0.f, 0.f};
            int nbi = un0 + g, nbg = 64 + un0 + g, nbo = 128 + un0 + g;
            #pragma unroll
            for (int ks = 0; ks < 2; ks++) {
                int kb = ks * 16;
                u32 bh0, bh1, bl0, bl1;
                bh0 = *(const u32*)(smc + F_B0HI + (nbi * 40 + kb + 2 * tig) * 2);
                bh1 = *(const u32*)(smc + F_B0HI + (nbi * 40 + kb + 8 + 2 * tig) * 2);
                bl0 = *(const u32*)(smc + F_B0LO + (nbi * 40 + kb + 2 * tig) * 2);
                bl1 = *(const u32*)(smc + F_B0LO + (nbi * 40 + kb + 8 + 2 * tig) * 2);
                mma_bf16(di, Ah[ks][0], Ah[ks][1], Ah[ks][2], Ah[ks][3], bh0, bh1);
                mma_bf16(di, Ah[ks][0], Ah[ks][1], Ah[ks][2], Ah[ks][3], bl0, bl1);
                mma_bf16(di, Al[ks][0], Al[ks][1], Al[ks][2], Al[ks][3], bh0, bh1);
                bh0 = *(const u32*)(smc + F_B0HI + (nbg * 40 + kb + 2 * tig) * 2);
                bh1 = *(const u32*)(smc + F_B0HI + (nbg * 40 + kb + 8 + 2 * tig) * 2);
                bl0 = *(const u32*)(smc + F_B0LO + (nbg * 40 + kb + 2 * tig) * 2);
                bl1 = *(const u32*)(smc + F_B0LO + (nbg * 40 + kb + 8 + 2 * tig) * 2);
                mma_bf16(dg, Ah[ks][0], Ah[ks][1], Ah[ks][2], Ah[ks][3], bh0, bh1);
                mma_bf16(dg, Ah[ks][0], Ah[ks][1], Ah[ks][2], Ah[ks][3], bl0, bl1);
                mma_bf16(dg, Al[ks][0], Al[ks][1], Al[ks][2], Al[ks][3], bh0, bh1);
                bh0 = *(const u32*)(smc + F_B0HI + (nbo * 40 + kb + 2 * tig) * 2);
                bh1 = *(const u32*)(smc + F_B0HI + (nbo * 40 + kb + 8 + 2 * tig) * 2);
                bl0 = *(const u32*)(smc + F_B0LO + (nbo * 40 + kb + 2 * tig) * 2);
                bl1 = *(const u32*)(smc + F_B0LO + (nbo * 40 + kb + 8 + 2 * tig) * 2);
                mma_bf16(dq, Ah[ks][0], Ah[ks][1], Ah[ks][2], Ah[ks][3], bh0, bh1);
                mma_bf16(dq, Ah[ks][0], Ah[ks][1], Ah[ks][2], Ah[ks][3], bl0, bl1);
                mma_bf16(dq, Al[ks][0], Al[ks][1], Al[ks][2], Al[ks][3], bh0, bh1);
            }
            int u0 = un0 + 2 * tig, u1 = u0 + 1;
            float vi0 = cV[u0],       vi1 = cV[u1];
            float vg0 = cV[64 + u0],  vg1 = cV[64 + u1];
            float vo0 = cV[128 + u0], vo1 = cV[128 + u1];
            float ci0 = cC0[u0],       ci1 = cC0[u1];
            float cg0 = cC0[64 + u0],  cg1 = cC0[64 + u1];
            float co0 = cC0[128 + u0], co1 = cC0[128 + u1];
            int base = (un0 >> 3) * 4;
            {
                float c0 = sigapx(di[0] + fmaf(ynA, vi0, ci0)) *
                           tanhapx(dg[0] + fmaf(ynA, vg0, cg0));
                float c1 = sigapx(di[1] + fmaf(ynA, vi1, ci1)) *
                           tanhapx(dg[1] + fmaf(ynA, vg1, cg1));
                h1reg[base + 0] = sigapx(dq[0] + fmaf(ynA, vo0, co0)) * tanhapx(c0);
                h1reg[base + 1] = sigapx(dq[1] + fmaf(ynA, vo1, co1)) * tanhapx(c1);
            }
            {
                float c0 = sigapx(di[2] + fmaf(ynB, vi0, ci0)) *
                           tanhapx(dg[2] + fmaf(ynB, vg0, cg0));
                float c1 = sigapx(di[3] + fmaf(ynB, vi1, ci1)) *
                           tanhapx(dg[3] + fmaf(ynB, vg1, cg1));
                h1reg[base + 2] = sigapx(dq[2] + fmaf(ynB, vo0, co0)) * tanhapx(c0);
                h1reg[base + 3] = sigapx(dq[3] + fmaf(ynB, vo1, co1)) * tanhapx(c1);
            }
        }
    }
    __syncthreads();   // phase1 region (X/B0) now dead everywhere

    // handoff: h1 registers -> bf16 hi/lo in A1 region (overlaps X/B0)
    #pragma unroll
    for (int gi = 0; gi < 8; gi++) {
        int u0 = gi * 8 + 2 * tig;
        float a0 = h1reg[gi * 4 + 0], a1 = h1reg[gi * 4 + 1];
        float b0 = h1reg[gi * 4 + 2], b1 = h1reg[gi * 4 + 3];
        __nv_bfloat16 a0h = __float2bfloat16(a0), a1h = __float2bfloat16(a1);
        __nv_bfloat16 b0h = __float2bfloat16(b0), b1h = __float2bfloat16(b1);
        u32 ahi = (u32)__bfloat16_as_ushort(a0h) | ((u32)__bfloat16_as_ushort(a1h) << 16);
        u32 bhi = (u32)__bfloat16_as_ushort(b0h) | ((u32)__bfloat16_as_ushort(b1h) << 16);
        u32 alo = pack_bf16x2(a0 - __bfloat162float(a0h), a1 - __bfloat162float(a1h));
        u32 blo = pack_bf16x2(b0 - __bfloat162float(b0h), b1 - __bfloat162float(b1h));
        *(u32*)(smc + F_A1HI + ((r0 + g) * 72 + u0) * 2)     = ahi;
        *(u32*)(smc + F_A1LO + ((r0 + g) * 72 + u0) * 2)     = alo;
        *(u32*)(smc + F_A1HI + ((r0 + g + 8) * 72 + u0) * 2) = bhi;
        *(u32*)(smc + F_A1LO + ((r0 + g + 8) * 72 + u0) * 2) = blo;
    }
    __syncthreads();

    // ---------------- Phase 2: layer1 MMA + head, register epilogue -----------
    u32 Ah[4][4], Al[4][4];
    #pragma unroll
    for (int ks = 0; ks < 4; ks++) {
        int kb = ks * 16;
        int ra = r0 + g, rb = r0 + g + 8;
        Ah[ks][0] = *(const u32*)(smc + F_A1HI + (ra * 72 + kb + 2 * tig) * 2);
        Ah[ks][1] = *(const u32*)(smc + F_A1HI + (rb * 72 + kb + 2 * tig) * 2);
        Ah[ks][2] = *(const u32*)(smc + F_A1HI + (ra * 72 + kb + 8 + 2 * tig) * 2);
        Ah[ks][3] = *(const u32*)(smc + F_A1HI + (rb * 72 + kb + 8 + 2 * tig) * 2);
        Al[ks][0] = *(const u32*)(smc + F_A1LO + (ra * 72 + kb + 2 * tig) * 2);
        Al[ks][1] = *(const u32*)(smc + F_A1LO + (rb * 72 + kb + 2 * tig) * 2);
        Al[ks][2] = *(const u32*)(smc + F_A1LO + (ra * 72 + kb + 8 + 2 * tig) * 2);
        Al[ks][3] = *(const u32*)(smc + F_A1LO + (rb * 72 + kb + 8 + 2 * tig) * 2);
    }

    float muA = 0.f, sgA = 0.f, muB = 0.f, sgB = 0.f;
    #pragma unroll 1
    for (int un0 = 0; un0 < 64; un0 += 8) {
        float di[4] = {0.f, 0.f, 0.f, 0.f};
        float dg[4] = {0.f, 0.f, 0.f, 0.f};
        float dq[4] = {0.f, 0.f, 0.f, 0.f};
        int nbi = un0 + g, nbg = 64 + un0 + g, nbo = 128 + un0 + g;
        #pragma unroll
        for (int ks = 0; ks < 4; ks++) {
            int kb = ks * 16;
            u32 bh0, bh1, bl0, bl1;
            bh0 = *(const u32*)(smc + F_B1HI + (nbi * 72 + kb + 2 * tig) * 2);
            bh1 = *(const u32*)(smc + F_B1HI + (nbi * 72 + kb + 8 + 2 * tig) * 2);
            bl0 = *(const u32*)(smc + F_B1LO + (nbi * 72 + kb + 2 * tig) * 2);
            bl1 = *(const u32*)(smc + F_B1LO + (nbi * 72 + kb + 8 + 2 * tig) * 2);
            mma_bf16(di, Ah[ks][0], Ah[ks][1], Ah[ks][2], Ah[ks][3], bh0, bh1);
            mma_bf16(di, Ah[ks][0], Ah[ks][1], Ah[ks][2], Ah[ks][3], bl0, bl1);
            mma_bf16(di, Al[ks][0], Al[ks][1], Al[ks][2], Al[ks][3], bh0, bh1);
            bh0 = *(const u32*)(smc + F_B1HI + (nbg * 72 + kb + 2 * tig) * 2);
            bh1 = *(const u32*)(smc + F_B1HI + (nbg * 72 + kb + 8 + 2 * tig) * 2);
            bl0 = *(const u32*)(smc + F_B1LO + (nbg * 72 + kb + 2 * tig) * 2);
            bl1 = *(const u32*)(smc + F_B1LO + (nbg * 72 + kb + 8 + 2 * tig) * 2);
            mma_bf16(dg, Ah[ks][0], Ah[ks][1], Ah[ks][2], Ah[ks][3], bh0, bh1);
            mma_bf16(dg, Ah[ks][0], Ah[ks][1], Ah[ks][2], Ah[ks][3], bl0, bl1);
            mma_bf16(dg, Al[ks][0], Al[ks][1], Al[ks][2], Al[ks][3], bh0, bh1);
            bh0 = *(const u32*)(smc + F_B1HI + (nbo * 72 + kb + 2 * tig) * 2);
            bh1 = *(const u32*)(smc + F_B1HI + (nbo * 72 + kb + 8 + 2 * tig) * 2);
            bl0 = *(const u32*)(smc + F_B1LO + (nbo * 72 + kb + 2 * tig) * 2);
            bl1 = *(const u32*)(smc + F_B1LO + (nbo * 72 + kb + 8 + 2 * tig) * 2);
            mma_bf16(dq, Ah[ks][0], Ah[ks][1], Ah[ks][2], Ah[ks][3], bh0, bh1);
            mma_bf16(dq, Ah[ks][0], Ah[ks][1], Ah[ks][2], Ah[ks][3], bl0, bl1);
            mma_bf16(dq, Al[ks][0], Al[ks][1], Al[ks][2], Al[ks][3], bh0, bh1);
        }
        int u0 = un0 + 2 * tig, u1 = u0 + 1;
        float ci0 = cC1[u0],       ci1 = cC1[u1];
        float cg0 = cC1[64 + u0],  cg1 = cC1[64 + u1];
        float co0 = cC1[128 + u0], co1 = cC1[128 + u1];
        float wm0 = cWM[u0], wm1 = cWM[u1];
        float ws0 = cWS[u0], ws1 = cWS[u1];
        {
            float c0 = sigapx(di[0] + ci0) * tanhapx(dg[0] + cg0);
            float h0 = fmaxf(sigapx(dq[0] + co0) * tanhapx(c0), 0.f);
            float c1 = sigapx(di[1] + ci1) * tanhapx(dg[1] + cg1);
            float h1 = fmaxf(sigapx(dq[1] + co1) * tanhapx(c1), 0.f);
            muA = fmaf(h0, wm0, muA); muA = fmaf(h1, wm1, muA);
            sgA = fmaf(h0, ws0, sgA); sgA = fmaf(h1, ws1, sgA);
        }
        {
            float c0 = sigapx(di[2] + ci0) * tanhapx(dg[2] + cg0);
            float h0 = fmaxf(sigapx(dq[2] + co0) * tanhapx(c0), 0.f);
            float c1 = sigapx(di[3] + ci1) * tanhapx(dg[3] + cg1);
            float h1 = fmaxf(sigapx(dq[3] + co1) * tanhapx(c1), 0.f);
            muB = fmaf(h0, wm0, muB); muB = fmaf(h1, wm1, muB);
            sgB = fmaf(h0, ws0, sgB); sgB = fmaf(h1, ws1, sgB);
        }
    }

    muA += __shfl_xor_sync(0xffffffffu, muA, 1);
    muA += __shfl_xor_sync(0xffffffffu, muA, 2);
    sgA += __shfl_xor_sync(0xffffffffu, sgA, 1);
    sgA += __shfl_xor_sync(0xffffffffu, sgA, 2);
    muB += __shfl_xor_sync(0xffffffffu, muB, 1);
    muB += __shfl_xor_sync(0xffffffffu, muB, 2);
    sgB += __shfl_xor_sync(0xffffffffu, sgB, 1);
    sgB += __shfl_xor_sync(0xffffffffu, sgB, 2);

    if (tig < 2) {
        int row = r0 + g + (tig ? 8 : 0);
        float mu = (tig ? muB : muA) + b_mu[0];
        float sg = (tig ? sgB : sgA) + b_sigma[0];
        int grow = rowbase + row;
        int n = grow / SEQL, t = grow - n * SEQL;
        float sigma = fsoftplus(sg) + 1e-6f;
        out_mu[n * TT + t] = mu;
        out_sg[n * TT + t] = sigma;
        if (t == SEQL - 1) {
            float yn = cY[row];
            float inv = __fdividef(1.f, sigma);
            float dd = yn - mu;
            float lik = 0.3989422804014327f * inv * __expf(-0.5f * dd * dd * inv * inv);
            out_yp[n * HOR] = lik;
            g_carry[n] = lik;
        }
    }
}

// =============================================================================
// P1b: layer0 x-part for forecast rows (FFMA2 path, unchanged)
#define SMA_W   0
#define SMA_X   6176
#define SMA_V   10528
#define SMA_C0  10720
#define SMA_FLOATS 10912
#define SMA_BYTES (SMA_FLOATS * 4)

#define GATE_FFMA2_16(wi2, wg2, wo2, xa, xb, xc, xd)                      \
    ai2[0]=ffma2(wi2, xa.x, ai2[0]); ai2[1]=ffma2(wi2, xa.y, ai2[1]);     \
    ai2[2]=ffma2(wi2, xb.x, ai2[2]); ai2[3]=ffma2(wi2, xb.y, ai2[3]);     \
    ai2[4]=ffma2(wi2, xc.x, ai2[4]); ai2[5]=ffma2(wi2, xc.y, ai2[5]);     \
    ai2[6]=ffma2(wi2, xd.x, ai2[6]); ai2[7]=ffma2(wi2, xd.y, ai2[7]);     \
    ag2[0]=ffma2(wg2, xa.x, ag2[0]); ag2[1]=ffma2(wg2, xa.y, ag2[1]);     \
    ag2[2]=ffma2(wg2, xb.x, ag2[2]); ag2[3]=ffma2(wg2, xb.y, ag2[3]);     \
    ag2[4]=ffma2(wg2, xc.x, ag2[4]); ag2[5]=ffma2(wg2, xc.y, ag2[5]);     \
    ag2[6]=ffma2(wg2, xd.x, ag2[6]); ag2[7]=ffma2(wg2, xd.y, ag2[7]);     \
    ao2[0]=ffma2(wo2, xa.x, ao2[0]); ao2[1]=ffma2(wo2, xa.y, ao2[1]);     \
    ao2[2]=ffma2(wo2, xb.x, ao2[2]); ao2[3]=ffma2(wo2, xb.y, ao2[3]);     \
    ao2[4]=ffma2(wo2, xc.x, ao2[4]); ao2[5]=ffma2(wo2, xc.y, ao2[5]);     \
    ao2[6]=ffma2(wo2, xd.x, ao2[6]); ao2[7]=ffma2(wo2, xd.y, ao2[7]);

__global__ void __launch_bounds__(256, 2) kP1b(
    const float* __restrict__ Xf,
    const float* __restrict__ W_ih, const float* __restrict__ b_ih,
    const float* __restrict__ b_hh, const float* __restrict__ b_embed)
{
    extern __shared__ float sm[];
    int tid = threadIdx.x;
    for (int i = tid; i < 6144; i += 256) {
        int g = i >> 11, u = (i >> 5) & 63, k = i & 31;
        sm[SMA_W + k * 193 + g * 64 + u] = W_ih[rowsel(g, u) * 64 + k];
    }
    for (int j = tid; j < 192; j += 256) {
        int g = j >> 6, u = j & 63, row = rowsel(g, u);
        float cb = 0.f;
        #pragma unroll
        for (int e = 0; e < 32; e++)
            cb = fmaf(W_ih[row * 64 + 32 + e], b_embed[e], cb);
        sm[SMA_C0 + j] = b_ih[row] + b_hh[row] + cb;
    }
    int tp = blockIdx.y, nbase = blockIdx.x * 128;
    for (int i = tid; i < 4096; i += 256) {
        int r = i >> 5, k = i & 31;
        sm[SMA_X + k * 132 + r] = Xf[((size_t)(nbase + r) * HOR + tp) * 32 + k];
    }
    __syncthreads();

    int u = tid & 63, rg = tid >> 6;
    float ci = sm[SMA_C0 + u], cg0 = sm[SMA_C0 + 64 + u], co = sm[SMA_C0 + 128 + u];

    #pragma unroll 1
    for (int rr = 0; rr < 2; rr++) {
        int r0 = rg * 32 + rr * 16;
        u64 ai2[8], ag2[8], ao2[8];
        #pragma unroll
        for (int p = 0; p < 8; p++) {
            ai2[p] = pack2(ci, ci);
            ag2[p] = pack2(cg0, cg0);
            ao2[p] = pack2(co, co);
        }
        #pragma unroll 4
        for (int k = 0; k < 32; k++) {
            float wi = sm[SMA_W + k * 193 + u];
            float wg = sm[SMA_W + k * 193 + 64 + u];
            float wo = sm[SMA_W + k * 193 + 128 + u];
            u64 wi2 = pack2(wi, wi), wg2 = pack2(wg, wg), wo2 = pack2(wo, wo);
            ulonglong2 xa = *(const ulonglong2*)&sm[SMA_X + k * 132 + r0];
            ulonglong2 xb = *(const ulonglong2*)&sm[SMA_X + k * 132 + r0 + 4];
            ulonglong2 xc = *(const ulonglong2*)&sm[SMA_X + k * 132 + r0 + 8];
            ulonglong2 xd = *(const ulonglong2*)&sm[SMA_X + k * 132 + r0 + 12];
            GATE_FFMA2_16(wi2, wg2, wo2, xa, xb, xc, xd)
        }
        u64* gi = (u64*)&g_Gx[((size_t)tp * 192 + u) * 4096 + nbase + r0];
        u64* gg = (u64*)&g_Gx[((size_t)tp * 192 + 64 + u) * 4096 + nbase + r0];
        u64* go = (u64*)&g_Gx[((size_t)tp * 192 + 128 + u) * 4096 + nbase + r0];
        #pragma unroll
        for (int p = 0; p < 4; p++) {
            *(ulonglong2*)(gi + 2 * p) = make_ulonglong2(ai2[2 * p], ai2[2 * p + 1]);
            *(ulonglong2*)(gg + 2 * p) = make_ulonglong2(ag2[2 * p], ag2[2 * p + 1]);
            *(ulonglong2*)(go + 2 * p) = make_ulonglong2(ao2[2 * p], ao2[2 * p + 1]);
        }
    }
}

// =============================================================================
// kB: 24-step recurrence (unchanged)
#define SMB_WJ  0
#define SMB_V   12288
#define SMB_C1  12480
#define SMB_WMU 12672
#define SMB_WSG 12736
#define SMB_H1  12800
#define SMB_PMU 14912
#define SMB_PSG 15440
#define SMB_YN  15968
#define SMB_FLOATS 16000
#define SMB_BYTES (SMB_FLOATS * 4)

__global__ void __launch_bounds__(512) kB(
    const float* __restrict__ W_ih, const float* __restrict__ b_ih,
    const float* __restrict__ b_hh, const float* __restrict__ W_embed,
    const float* __restrict__ b_embed, const float* __restrict__ W_mu,
    const float* __restrict__ b_mu, const float* __restrict__ W_sigma,
    const float* __restrict__ b_sigma,
    float* __restrict__ out_yp, float* __restrict__ out_mu,
    float* __restrict__ out_sg)
{
    extern __shared__ float sm[];
    int tid = threadIdx.x;
    for (int i = tid; i < 12288; i += 512) {
        int g = i >> 12, u = (i >> 6) & 63, k = i & 63;
        sm[SMB_WJ + (g * 64 + u) * 64 + k] = W_ih[16384 + rowsel(g, u) * 64 + k];
    }
    for (int j = tid; j < 192; j += 512) {
        int g = j >> 6, u = j & 63, row = rowsel(g, u);
        float v = 0.f;
        #pragma unroll
        for (int e = 0; e < 32; e++)
            v = fmaf(W_ih[row * 64 + 32 + e], W_embed[e], v);
        sm[SMB_V + j] = v;
        sm[SMB_C1 + j] = b_ih[256 + row] + b_hh[256 + row];
    }
    for (int i = tid; i < 64; i += 512) {
        sm[SMB_WMU + i] = W_mu[i];
        sm[SMB_WSG + i] = W_sigma[i];
    }
    __syncthreads();

    int w = tid >> 5, s = tid & 31;
    int n = blockIdx.x * 32 + s, ub = w * 4;
    float yn = g_carry[n];
    float bmu = b_mu[0], bsg = b_sigma[0];

    #pragma unroll 1
    for (int t = SEQL; t < TT; t++) {
        int tp = t - SEQL;
        const float* gx = g_Gx + (size_t)tp * 192 * 4096 + n;
        #pragma unroll
        for (int j = 0; j < 4; j++) {
            int uu = ub + j;
            float ai = fmaf(yn, sm[SMB_V + uu], gx[uu * 4096]);
            float ag = fmaf(yn, sm[SMB_V + 64 + uu], gx[(64 + uu) * 4096]);
            float ao = fmaf(yn, sm[SMB_V + 128 + uu], gx[(128 + uu) * 4096]);
            float c = sigapx(ai) * tanhapx(ag);
            sm[SMB_H1 + s * 66 + uu] = sigapx(ao) * tanhapx(c);
        }
        __syncthreads();
        u64 hp[32];
        #pragma unroll
        for (int k2 = 0; k2 < 32; k2++)
            hp[k2] = *(const u64*)&sm[SMB_H1 + s * 66 + 2 * k2];
        float pmu = 0.f, psg = 0.f;
        #pragma unroll
        for (int j = 0; j < 4; j++) {
            int uu = ub + j;
            u64 ai2 = pack2(sm[SMB_C1 + uu], 0.f);
            u64 ag2 = pack2(sm[SMB_C1 + 64 + uu], 0.f);
            u64 ao2 = pack2(sm[SMB_C1 + 128 + uu], 0.f);
            const ulonglong2* wiv = (const ulonglong2*)&sm[SMB_WJ + uu * 64];
            const ulonglong2* wgv = (const ulonglong2*)&sm[SMB_WJ + (64 + uu) * 64];
            const ulonglong2* wov = (const ulonglong2*)&sm[SMB_WJ + (128 + uu) * 64];
            #pragma unroll
            for (int k4 = 0; k4 < 16; k4++) {
                ulonglong2 a = wiv[k4], b = wgv[k4], cw = wov[k4];
                u64 h0 = hp[2 * k4], h1v = hp[2 * k4 + 1];
                ai2 = ffma2(h0, a.x, ai2);  ai2 = ffma2(h1v, a.y, ai2);
                ag2 = ffma2(h0, b.x, ag2);  ag2 = ffma2(h1v, b.y, ag2);
                ao2 = ffma2(h0, cw.x, ao2); ao2 = ffma2(h1v, cw.y, ao2);
            }
            float al, ah, gl, gh, ol, oh;
            unpack2(ai2, al, ah); unpack2(ag2, gl, gh); unpack2(ao2, ol, oh);
            float ai = al + ah, ag = gl + gh, ao = ol + oh;
            float c = sigapx(ai) * tanhapx(ag);
            float h2 = fmaxf(sigapx(ao) * tanhapx(c), 0.f);
            pmu = fmaf(h2, sm[SMB_WMU + uu], pmu);
            psg = fmaf(h2, sm[SMB_WSG + uu], psg);
        }
        sm[SMB_PMU + w * 33 + s] = pmu;
        sm[SMB_PSG + w * 33 + s] = psg;
        __syncthreads();
        if (tid < 32) {
            float mu = bmu, sg = bsg;
            #pragma unroll
            for (int w2 = 0; w2 < 16; w2++) {
                mu += sm[SMB_PMU + w2 * 33 + s];
                sg += sm[SMB_PSG + w2 * 33 + s];
            }
            float sigma = fsoftplus(sg) + 1e-6f;
            out_mu[n * TT + t] = mu;
            out_sg[n * TT + t] = sigma;
            float inv = __fdividef(1.f, sigma);
            float d = yn - mu;
            float lik = 0.3989422804014327f * inv * __expf(-0.5f * d * d * inv * inv);
            if (t < TT - 1) out_yp[n * HOR + tp + 1] = lik;
            sm[SMB_YN + s] = lik;
        }
        __syncthreads();
        yn = sm[SMB_YN + s];
    }
}

// =============================================================================
extern "C" void kernel_launch(void* const* d_in, const int* in_sizes, int n_in,
                              void* d_out, int out_size)
{
    (void)in_sizes; (void)n_in;
    const float* X       = (const float*)d_in[0];
    const float* y       = (const float*)d_in[1];
    const float* Xf      = (const float*)d_in[2];
    const float* W_embed = (const float*)d_in[3];
    const float* b_embed = (const float*)d_in[4];
    const float* W_ih    = (const float*)d_in[5];
    const float* b_ih    = (const float*)d_in[6];
    const float* b_hh    = (const float*)d_in[7];
    const float* W_mu    = (const float*)d_in[8];
    const float* b_mu    = (const float*)d_in[9];
    const float* W_sigma = (const float*)d_in[10];
    const float* b_sigma = (const float*)d_in[11];

    float* out = (float*)d_out;
    float* yp = out;
    float* omu;
    float* osg;
    const int full = NTS * HOR + 2 * NTS * TT;
    if (out_size >= full) {
        omu = out + NTS * HOR;
        osg = omu + NTS * TT;
    } else {
        void* p0; void* p1;
        cudaGetSymbolAddress(&p0, g_mu_fb);
        cudaGetSymbolAddress(&p1, g_sg_fb);
        omu = (float*)p0; osg = (float*)p1;
    }

    cudaFuncSetAttribute(kPf,  cudaFuncAttributeMaxDynamicSharedMemorySize, F_BYTES);
    cudaFuncSetAttribute(kP1b, cudaFuncAttributeMaxDynamicSharedMemorySize, SMA_BYTES);
    cudaFuncSetAttribute(kB,   cudaFuncAttributeMaxDynamicSharedMemorySize, SMB_BYTES);

    kPrepB<<<(192 * 96 + 192 + 255) / 256, 256>>>(W_ih, W_embed, b_embed, b_ih, b_hh);
    kP1b<<<dim3(NTS / 128, HOR), 256, SMA_BYTES>>>(Xf, W_ih, b_ih, b_hh, b_embed);
    kPf<<<TR / 128, 256, F_BYTES>>>(X, y, W_mu, b_mu, W_sigma, b_sigma,
                                    yp, omu, osg);
    kB<<<NTS / 32, 512, SMB_BYTES>>>(W_ih, b_ih, b_hh, W_embed, b_embed,
                                     W_mu, b_mu, W_sigma, b_sigma, yp, omu, osg);
}